// round 8
// baseline (speedup 1.0000x reference)
#include <cuda_runtime.h>
#include <cuda_bf16.h>
#include <cstdint>

#define D_MODEL 1024
#define N_HEADS 16
#define HEAD_DIM 64
#define BATCH 4
#define SEQ 2048
#define M_TOT 8192  // BATCH*SEQ

// ---- scratch (device globals per allocation-free rule) ----
__device__ uint32_t g_x8h[M_TOT * 256];      // x int8 hi-digit plane (4 k per u32)
__device__ uint32_t g_x8l[M_TOT * 256];      // x int8 lo-digit plane
__device__ float g_sx[M_TOT];                // x per-row scales
__device__ uint32_t g_W8h[4 * 1024 * 256];   // W hi planes (4 matrices)
__device__ uint32_t g_W8l[4 * 1024 * 256];   // W lo planes
__device__ float g_sW[4 * 1024];             // W per-row scales
__device__ uint2 g_Qh[M_TOT * 512];          // Q scatter (B,H,S,32) interleaved {hi2,lo2} bf16
__device__ uint2 g_Kh[M_TOT * 512];          // K scatter
__device__ uint32_t g_Vh[M_TOT * 512];       // V scatter hi plane (B,H,S,32 u32-pairs) bf16
__device__ uint32_t g_Vl[M_TOT * 512];       // V scatter lo plane
__device__ float g_Af[M_TOT * D_MODEL];      // attention out fp32 (B,S,D)
__device__ uint32_t g_A8h[M_TOT * 256];      // attention out quantized hi
__device__ uint32_t g_A8l[M_TOT * 256];      // attention out quantized lo
__device__ float g_sA[M_TOT];                // attention out scales

// ---------- helpers ----------
__device__ __forceinline__ uint2 split2(float f0, float f1) {
    __nv_bfloat16 h0 = __float2bfloat16_rn(f0), h1 = __float2bfloat16_rn(f1);
    float r0 = f0 - __bfloat162float(h0), r1 = f1 - __bfloat162float(h1);
    __nv_bfloat16 l0 = __float2bfloat16_rn(r0), l1 = __float2bfloat16_rn(r1);
    uint2 u;
    u.x = ((uint32_t)__bfloat16_as_ushort(h1) << 16) | __bfloat16_as_ushort(h0);
    u.y = ((uint32_t)__bfloat16_as_ushort(l1) << 16) | __bfloat16_as_ushort(l0);
    return u;
}

__device__ __forceinline__ void mma_bf16(float c[4], uint32_t a0, uint32_t a1, uint32_t a2, uint32_t a3,
                                         uint32_t b0, uint32_t b1) {
    asm volatile(
        "mma.sync.aligned.m16n8k16.row.col.f32.bf16.bf16.f32 "
        "{%0,%1,%2,%3}, {%4,%5,%6,%7}, {%8,%9}, {%0,%1,%2,%3};\n"
        : "+f"(c[0]), "+f"(c[1]), "+f"(c[2]), "+f"(c[3])
        : "r"(a0), "r"(a1), "r"(a2), "r"(a3), "r"(b0), "r"(b1));
}

__device__ __forceinline__ void mma_s8(int c[4], uint32_t a0, uint32_t a1, uint32_t a2, uint32_t a3,
                                       uint32_t b0, uint32_t b1) {
    asm volatile(
        "mma.sync.aligned.m16n8k32.row.col.s32.s8.s8.s32 "
        "{%0,%1,%2,%3}, {%4,%5,%6,%7}, {%8,%9}, {%0,%1,%2,%3};\n"
        : "+r"(c[0]), "+r"(c[1]), "+r"(c[2]), "+r"(c[3])
        : "r"(a0), "r"(a1), "r"(a2), "r"(a3), "r"(b0), "r"(b1));
}

__device__ __forceinline__ void ldmx4t(uint32_t &b0, uint32_t &b1, uint32_t &b2, uint32_t &b3, uint32_t addr) {
    asm volatile("ldmatrix.sync.aligned.m8n8.x4.trans.shared.b16 {%0,%1,%2,%3}, [%4];"
                 : "=r"(b0), "=r"(b1), "=r"(b2), "=r"(b3)
                 : "r"(addr));
}

__device__ __forceinline__ void cpa8(uint32_t saddr, const void *g) {
    asm volatile("cp.async.ca.shared.global [%0], [%1], 8;\n" ::"r"(saddr), "l"(g));
}
__device__ __forceinline__ void cpa16(uint32_t saddr, const void *g) {
    asm volatile("cp.async.cg.shared.global [%0], [%1], 16;\n" ::"r"(saddr), "l"(g));
}

// ---------- quantize: fp32 row -> 2-digit int8 planes + per-row scale ----------
__device__ __forceinline__ void quant_row(const float *__restrict__ src, uint32_t *__restrict__ dh,
                                          uint32_t *__restrict__ dl, float *__restrict__ sOut, int row, int tid) {
    __shared__ float red[8];
    float4 v = *(const float4 *)(src + 4 * tid);
    float m = fmaxf(fmaxf(fabsf(v.x), fabsf(v.y)), fmaxf(fabsf(v.z), fabsf(v.w)));
#pragma unroll
    for (int o = 16; o > 0; o >>= 1) m = fmaxf(m, __shfl_xor_sync(0xffffffffu, m, o));
    if ((tid & 31) == 0) red[tid >> 5] = m;
    __syncthreads();
    if (tid < 8) {
        float t = red[tid];
#pragma unroll
        for (int o = 4; o > 0; o >>= 1) t = fmaxf(t, __shfl_xor_sync(0xffu, t, o));
        if (tid == 0) red[0] = fmaxf(t, 1e-20f);
    }
    __syncthreads();
    float maxv = red[0];
    float s = maxv / 16255.f;
    float inv = 16255.f / maxv;
    int q[4], h[4], l[4];
    float vv[4] = {v.x, v.y, v.z, v.w};
#pragma unroll
    for (int j = 0; j < 4; j++) {
        q[j] = (int)rintf(vv[j] * inv);
        q[j] = max(-16255, min(16255, q[j]));
        h[j] = (q[j] + 64) >> 7;
        l[j] = q[j] - (h[j] << 7);
    }
    dh[tid] = (h[0] & 0xFF) | ((h[1] & 0xFF) << 8) | ((h[2] & 0xFF) << 16) | ((uint32_t)(h[3] & 0xFF) << 24);
    dl[tid] = (l[0] & 0xFF) | ((l[1] & 0xFF) << 8) | ((l[2] & 0xFF) << 16) | ((uint32_t)(l[3] & 0xFF) << 24);
    if (tid == 0) sOut[row] = s;
}

__global__ void __launch_bounds__(256) quant_kernel(const float *__restrict__ src, uint32_t *__restrict__ dh,
                                                    uint32_t *__restrict__ dl, float *__restrict__ sOut) {
    int row = blockIdx.x;
    quant_row(src + (size_t)row * 1024, dh + (size_t)row * 256, dl + (size_t)row * 256, sOut, row, threadIdx.x);
}

__global__ void __launch_bounds__(256) quant_w4_kernel(const float *__restrict__ W0, const float *__restrict__ W1,
                                                       const float *__restrict__ W2, const float *__restrict__ W3,
                                                       uint32_t *__restrict__ dh, uint32_t *__restrict__ dl,
                                                       float *__restrict__ sOut) {
    int row = blockIdx.x;  // 0..4095
    const float *W = (row < 1024) ? W0 : (row < 2048) ? W1 : (row < 3072) ? W2 : W3;
    quant_row(W + (size_t)(row & 1023) * 1024, dh + (size_t)row * 256, dl + (size_t)row * 256, sOut, row,
              threadIdx.x);
}

// ---------- int8 GEMM: C[m,n] = sA[m]*sB[n]*(16384*hh + 128*(hl+lh)) ----------
// BM=BN=128, Ktile=64. smem planes [128 rows][20 u32] per plane; 4 planes/stage, 2 stages.
#define RS 20               // row stride in u32
#define PL (128 * RS * 4)   // plane bytes 10240
#define STG8 (4 * PL)       // stage bytes 40960
#define GEMM8_SMEM (2 * STG8)

__global__ void __launch_bounds__(256) gemm8_kernel(const uint32_t *__restrict__ Ah, const uint32_t *__restrict__ Al,
                                                    const float *__restrict__ sA, const uint32_t *__restrict__ Bh,
                                                    const uint32_t *__restrict__ Bl, const float *__restrict__ sB,
                                                    void *__restrict__ Cout, void *__restrict__ Cout2, int mode) {
    extern __shared__ char sm8[];
    uint32_t smb;
    asm("{ .reg .u64 t; cvta.to.shared.u64 t, %1; cvt.u32.u64 %0, t; }" : "=r"(smb) : "l"(sm8));
    const uint32_t *smu = (const uint32_t *)sm8;
    const int tid = threadIdx.x, lane = tid & 31, w = tid >> 5;
    const int m0 = blockIdx.y * 128, n0 = blockIdx.x * 128;
    const int wm = (w >> 2) * 64, wn = (w & 3) * 32;
    const int gr = lane >> 2, gc = lane & 3;

    int hh[4][4][4], xx[4][4][4];
#pragma unroll
    for (int i = 0; i < 4; i++)
#pragma unroll
        for (int j = 0; j < 4; j++)
#pragma unroll
            for (int k = 0; k < 4; k++) { hh[i][j][k] = 0; xx[i][j][k] = 0; }

    auto load = [&](int kt, int stg) {
        const uint32_t SB = smb + stg * STG8;
#pragma unroll
        for (int i = 0; i < 8; i++) {
            int id = tid + i * 256;          // 0..2047
            int plane = id >> 9;             // 0 Ah, 1 Al, 2 Bh, 3 Bl
            int rid = id & 511;
            int r = rid >> 2, j = rid & 3;   // 16B chunk -> u32 col 4j
            const uint32_t *g;
            if (plane == 0)      g = Ah + (size_t)(m0 + r) * 256;
            else if (plane == 1) g = Al + (size_t)(m0 + r) * 256;
            else if (plane == 2) g = Bh + (size_t)(n0 + r) * 256;
            else                 g = Bl + (size_t)(n0 + r) * 256;
            cpa16(SB + plane * PL + (r * RS + 4 * j) * 4, g + kt * 16 + 4 * j);
        }
    };

    load(0, 0);
    asm volatile("cp.async.commit_group;\n");

    for (int kt = 0; kt < 16; ++kt) {
        asm volatile("cp.async.wait_group 0;\n");
        __syncthreads();
        if (kt + 1 < 16) {
            load(kt + 1, (kt + 1) & 1);
            asm volatile("cp.async.commit_group;\n");
        }
        const uint32_t *Sh = smu + ((kt & 1) * STG8) / 4;
        const uint32_t *pAh = Sh, *pAl = Sh + PL / 4, *pBh = Sh + 2 * PL / 4, *pBl = Sh + 3 * PL / 4;
#pragma unroll
        for (int sub = 0; sub < 2; sub++) {
            const int so = sub * 8;
            uint32_t ah[4][4], al[4][4], bh[4][2], bl[4][2];
#pragma unroll
            for (int im = 0; im < 4; im++) {
                int base = (wm + im * 16 + gr) * RS + so + gc;
                ah[im][0] = pAh[base]; ah[im][1] = pAh[base + 8 * RS];
                ah[im][2] = pAh[base + 4]; ah[im][3] = pAh[base + 8 * RS + 4];
                al[im][0] = pAl[base]; al[im][1] = pAl[base + 8 * RS];
                al[im][2] = pAl[base + 4]; al[im][3] = pAl[base + 8 * RS + 4];
            }
#pragma unroll
            for (int in = 0; in < 4; in++) {
                int base = (wn + in * 8 + gr) * RS + so + gc;
                bh[in][0] = pBh[base]; bh[in][1] = pBh[base + 4];
                bl[in][0] = pBl[base]; bl[in][1] = pBl[base + 4];
            }
#pragma unroll
            for (int im = 0; im < 4; im++)
#pragma unroll
                for (int in = 0; in < 4; in++) {
                    mma_s8(hh[im][in], ah[im][0], ah[im][1], ah[im][2], ah[im][3], bh[in][0], bh[in][1]);
                    mma_s8(xx[im][in], ah[im][0], ah[im][1], ah[im][2], ah[im][3], bl[in][0], bl[in][1]);
                    mma_s8(xx[im][in], al[im][0], al[im][1], al[im][2], al[im][3], bh[in][0], bh[in][1]);
                }
        }
        __syncthreads();
    }

#pragma unroll
    for (int im = 0; im < 4; im++) {
        int m = m0 + wm + im * 16 + gr;
        float sa0 = sA[m], sa1 = sA[m + 8];
#pragma unroll
        for (int in = 0; in < 4; in++) {
            int gn = n0 + wn + in * 8 + gc * 2;
            float sb0 = sB[gn], sb1 = sB[gn + 1];
            float c0 = fmaf(16384.f, (float)hh[im][in][0], 128.f * (float)xx[im][in][0]) * sa0 * sb0;
            float c1 = fmaf(16384.f, (float)hh[im][in][1], 128.f * (float)xx[im][in][1]) * sa0 * sb1;
            float c2 = fmaf(16384.f, (float)hh[im][in][2], 128.f * (float)xx[im][in][2]) * sa1 * sb0;
            float c3 = fmaf(16384.f, (float)hh[im][in][3], 128.f * (float)xx[im][in][3]) * sa1 * sb1;
            if (mode == 0) {
                float *Cf = (float *)Cout;
                *(float2 *)(Cf + (size_t)m * 1024 + gn) = make_float2(c0, c1);
                *(float2 *)(Cf + (size_t)(m + 8) * 1024 + gn) = make_float2(c2, c3);
            } else {
                int b = m >> 11, s2 = m & 2047, h = gn >> 6, dd = gn & 63;
                if (mode == 1) {
                    uint2 *Ch = (uint2 *)Cout;
                    uint2 *dst = Ch + ((size_t)((b << 4) | h) * 2048 + s2) * 32 + (dd >> 1);
                    dst[0] = split2(c0, c1);
                    dst[8 * 32] = split2(c2, c3);
                } else {
                    uint32_t *Vh = (uint32_t *)Cout, *Vl = (uint32_t *)Cout2;
                    size_t idx = ((size_t)((b << 4) | h) * 2048 + s2) * 32 + (dd >> 1);
                    uint2 uA = split2(c0, c1);
                    Vh[idx] = uA.x; Vl[idx] = uA.y;
                    uint2 uB = split2(c2, c3);
                    Vh[idx + 8 * 32] = uB.x; Vl[idx + 8 * 32] = uB.y;
                }
            }
        }
    }
}

// ---------- Flash attention (bf16x3): q-tile 128, kv-tile 64 double-buffered; fp32 out ----------
#define LQ 35
#define QS_OFF 0
#define KS_OFF 35840
#define VH_OFF 71680
#define VL_OFF 90112
#define ATTN_SMEM 108544

__global__ void __launch_bounds__(256, 2) attn_kernel(const uint2 *__restrict__ Q, const uint2 *__restrict__ K,
                                                      const uint32_t *__restrict__ Vh,
                                                      const uint32_t *__restrict__ Vl, float *__restrict__ Of) {
    extern __shared__ char smab[];
    uint32_t smb;
    asm("{ .reg .u64 t; cvta.to.shared.u64 t, %1; cvt.u32.u64 %0, t; }" : "=r"(smb) : "l"(smab));
    uint2 *Qs = (uint2 *)smab;
    const int tid = threadIdx.x, lane = tid & 31, w = tid >> 5;
    const int qt = (int)gridDim.x - 1 - (int)blockIdx.x;
    const int bh = blockIdx.y;
    const int gr = lane >> 2, gc = lane & 3;
    const size_t hb = (size_t)bh * SEQ;
    const uint32_t vrow = ((lane >> 3) & 1) * 8 + (lane & 7);
    const uint32_t vcol = (lane >> 4) * 8;

    {
        const uint2 *Qg = Q + (hb + qt * 128) * 32;
#pragma unroll
        for (int i = 0; i < 16; i++) {
            int id = tid + i * 256;
            int r = id >> 5, c = id & 31;
            Qs[r * LQ + c] = Qg[r * 32 + c];
        }
    }

    auto loadKV = [&](int kt, int s) {
        const uint2 *Kg = K + (hb + kt * 64) * 32;
        const uint32_t kb = smb + KS_OFF + s * 17920;
#pragma unroll
        for (int i = 0; i < 8; i++) {
            int id = tid + i * 256;
            int r = id >> 5, c = id & 31;
            cpa8(kb + (r * LQ + c) * 8, Kg + r * 32 + c);
        }
        const uint32_t *Vhg = Vh + (hb + kt * 64) * 32;
        const uint32_t *Vlg = Vl + (hb + kt * 64) * 32;
        const uint32_t vhb = smb + VH_OFF + s * 9216;
        const uint32_t vlb = smb + VL_OFF + s * 9216;
#pragma unroll
        for (int i = 0; i < 2; i++) {
            int id = tid + i * 256;
            int r = id >> 3, c = id & 7;
            cpa16(vhb + r * 144 + c * 16, Vhg + r * 32 + c * 4);
            cpa16(vlb + r * 144 + c * 16, Vlg + r * 32 + c * 4);
        }
    };

    float accO[8][4];
#pragma unroll
    for (int i = 0; i < 8; i++)
#pragma unroll
        for (int j = 0; j < 4; j++) accO[i][j] = 0.f;
    float m0r = -1e30f, m1r = -1e30f, l0 = 0.f, l1 = 0.f;
    const int qlast = qt * 128 + w * 16 + 15;
    const int nkt = 2 * qt + 2;

    loadKV(0, 0);
    asm volatile("cp.async.commit_group;\n");

    for (int kt = 0; kt < nkt; ++kt) {
        const int s = kt & 1;
        __syncthreads();
        if (kt + 1 < nkt) {
            loadKV(kt + 1, s ^ 1);
            asm volatile("cp.async.commit_group;\n");
            asm volatile("cp.async.wait_group 1;\n");
        } else {
            asm volatile("cp.async.wait_group 0;\n");
        }
        __syncthreads();
        if (kt * 64 > qlast) continue;

        const uint2 *Ks = (const uint2 *)(smab + KS_OFF + s * 17920);
        const uint32_t vhb = smb + VH_OFF + s * 9216;
        const uint32_t vlb = smb + VL_OFF + s * 9216;

        float sr[8][4];
#pragma unroll
        for (int nt = 0; nt < 8; nt++)
#pragma unroll
            for (int j = 0; j < 4; j++) sr[nt][j] = 0.f;

#pragma unroll
        for (int ks = 0; ks < 4; ks++) {
            const int so = ks * 8;
            const uint2 *ap = Qs + (w * 16 + gr) * LQ + so + gc;
            uint2 a0 = ap[0], a1 = ap[8 * LQ], a2 = ap[4], a3 = ap[8 * LQ + 4];
#pragma unroll
            for (int nt = 0; nt < 8; nt++) {
                const uint2 *bp = Ks + (nt * 8 + gr) * LQ + so + gc;
                uint2 b0 = bp[0], b1 = bp[4];
                mma_bf16(sr[nt], a0.x, a1.x, a2.x, a3.x, b0.x, b1.x);
                mma_bf16(sr[nt], a0.y, a1.y, a2.y, a3.y, b0.x, b1.x);
                mma_bf16(sr[nt], a0.x, a1.x, a2.x, a3.x, b0.y, b1.y);
            }
        }

        const bool needm = (kt * 64 + 63) > (qt * 128 + w * 16);
        const int qg0 = qt * 128 + w * 16 + gr;
        float mx0 = -1e30f, mx1 = -1e30f;
#pragma unroll
        for (int nt = 0; nt < 8; nt++) {
            int kg = kt * 64 + nt * 8 + gc * 2;
#pragma unroll
            for (int j = 0; j < 4; j++) {
                float v = sr[nt][j] * 0.125f;
                if (needm && (kg + (j & 1)) > (qg0 + ((j >> 1) << 3))) v = -1e30f;
                sr[nt][j] = v;
            }
            mx0 = fmaxf(mx0, fmaxf(sr[nt][0], sr[nt][1]));
            mx1 = fmaxf(mx1, fmaxf(sr[nt][2], sr[nt][3]));
        }
        mx0 = fmaxf(mx0, __shfl_xor_sync(0xffffffffu, mx0, 1));
        mx0 = fmaxf(mx0, __shfl_xor_sync(0xffffffffu, mx0, 2));
        mx1 = fmaxf(mx1, __shfl_xor_sync(0xffffffffu, mx1, 1));
        mx1 = fmaxf(mx1, __shfl_xor_sync(0xffffffffu, mx1, 2));
        float mn0 = fmaxf(m0r, mx0), mn1 = fmaxf(m1r, mx1);
        float alpha0 = __expf(m0r - mn0), alpha1 = __expf(m1r - mn1);
        m0r = mn0; m1r = mn1;

        float rs0 = 0.f, rs1 = 0.f;
#pragma unroll
        for (int nt = 0; nt < 8; nt++) {
            float p0 = __expf(sr[nt][0] - mn0);
            float p1 = __expf(sr[nt][1] - mn0);
            float p2 = __expf(sr[nt][2] - mn1);
            float p3 = __expf(sr[nt][3] - mn1);
            sr[nt][0] = p0; sr[nt][1] = p1; sr[nt][2] = p2; sr[nt][3] = p3;
            rs0 += p0 + p1;
            rs1 += p2 + p3;
        }
        rs0 += __shfl_xor_sync(0xffffffffu, rs0, 1);
        rs0 += __shfl_xor_sync(0xffffffffu, rs0, 2);
        rs1 += __shfl_xor_sync(0xffffffffu, rs1, 1);
        rs1 += __shfl_xor_sync(0xffffffffu, rs1, 2);
        l0 = l0 * alpha0 + rs0;
        l1 = l1 * alpha1 + rs1;
#pragma unroll
        for (int nt = 0; nt < 8; nt++) {
            accO[nt][0] *= alpha0; accO[nt][1] *= alpha0;
            accO[nt][2] *= alpha1; accO[nt][3] *= alpha1;
        }

#pragma unroll
        for (int t = 0; t < 4; t++) {
            uint2 u0 = split2(sr[2 * t][0], sr[2 * t][1]);
            uint2 u1 = split2(sr[2 * t][2], sr[2 * t][3]);
            uint2 u2 = split2(sr[2 * t + 1][0], sr[2 * t + 1][1]);
            uint2 u3 = split2(sr[2 * t + 1][2], sr[2 * t + 1][3]);
            const uint32_t rowoff = (t * 16 + vrow) * 144 + vcol * 2;
#pragma unroll
            for (int ntp = 0; ntp < 4; ntp++) {
                uint32_t bh0, bh1, bh2, bh3, bl0, bl1, bl2, bl3;
                ldmx4t(bh0, bh1, bh2, bh3, vhb + rowoff + ntp * 32);
                ldmx4t(bl0, bl1, bl2, bl3, vlb + rowoff + ntp * 32);
                mma_bf16(accO[2 * ntp], u0.x, u1.x, u2.x, u3.x, bh0, bh1);
                mma_bf16(accO[2 * ntp], u0.y, u1.y, u2.y, u3.y, bh0, bh1);
                mma_bf16(accO[2 * ntp], u0.x, u1.x, u2.x, u3.x, bl0, bl1);
                mma_bf16(accO[2 * ntp + 1], u0.x, u1.x, u2.x, u3.x, bh2, bh3);
                mma_bf16(accO[2 * ntp + 1], u0.y, u1.y, u2.y, u3.y, bh2, bh3);
                mma_bf16(accO[2 * ntp + 1], u0.x, u1.x, u2.x, u3.x, bl2, bl3);
            }
        }
    }

    // epilogue: fp32 concat layout (B,S,D)
    float inv0 = 1.f / l0, inv1 = 1.f / l1;
    int b = bh >> 4, h = bh & 15;
    int q0 = qt * 128 + w * 16 + gr;
#pragma unroll
    for (int nt = 0; nt < 8; nt++) {
        int col = h * 64 + nt * 8 + gc * 2;
        float *o0 = Of + (size_t)(b * SEQ + q0) * 1024 + col;
        *(float2 *)o0 = make_float2(accO[nt][0] * inv0, accO[nt][1] * inv0);
        *(float2 *)(o0 + 8 * 1024) = make_float2(accO[nt][2] * inv1, accO[nt][3] * inv1);
    }
}

// ---------- launch ----------
extern "C" void kernel_launch(void *const *d_in, const int *in_sizes, int n_in, void *d_out, int out_size) {
    const float *x = (const float *)d_in[0];
    const float *Wq = (const float *)d_in[1];
    const float *Wk = (const float *)d_in[2];
    const float *Wv = (const float *)d_in[3];
    const float *Wo = (const float *)d_in[4];
    float *out = (float *)d_out;

    uint32_t *pxh, *pxl, *pWh, *pWl, *pVh, *pVl, *pAh, *pAl;
    float *psx, *psW, *psA, *pAf;
    uint2 *pQ, *pK;
    cudaGetSymbolAddress((void **)&pxh, g_x8h);
    cudaGetSymbolAddress((void **)&pxl, g_x8l);
    cudaGetSymbolAddress((void **)&psx, g_sx);
    cudaGetSymbolAddress((void **)&pWh, g_W8h);
    cudaGetSymbolAddress((void **)&pWl, g_W8l);
    cudaGetSymbolAddress((void **)&psW, g_sW);
    cudaGetSymbolAddress((void **)&pQ, g_Qh);
    cudaGetSymbolAddress((void **)&pK, g_Kh);
    cudaGetSymbolAddress((void **)&pVh, g_Vh);
    cudaGetSymbolAddress((void **)&pVl, g_Vl);
    cudaGetSymbolAddress((void **)&pAf, g_Af);
    cudaGetSymbolAddress((void **)&pAh, g_A8h);
    cudaGetSymbolAddress((void **)&pAl, g_A8l);
    cudaGetSymbolAddress((void **)&psA, g_sA);

    cudaFuncSetAttribute(gemm8_kernel, cudaFuncAttributeMaxDynamicSharedMemorySize, GEMM8_SMEM);
    cudaFuncSetAttribute(attn_kernel, cudaFuncAttributeMaxDynamicSharedMemorySize, ATTN_SMEM);

    dim3 gg(8, 64);
    // launch 1: quantize x; launch 2: quantize all W
    quant_kernel<<<M_TOT, 256>>>(x, pxh, pxl, psx);
    quant_w4_kernel<<<4096, 256>>>(Wq, Wk, Wv, Wo, pWh, pWl, psW);
    // launches 3-5: Q, K, V projections (int8)
    gemm8_kernel<<<gg, 256, GEMM8_SMEM>>>(pxh, pxl, psx, pWh + 0 * 1024 * 256, pWl + 0 * 1024 * 256, psW + 0 * 1024,
                                          pQ, nullptr, 1);
    gemm8_kernel<<<gg, 256, GEMM8_SMEM>>>(pxh, pxl, psx, pWh + 1 * 1024 * 256, pWl + 1 * 1024 * 256, psW + 1 * 1024,
                                          pK, nullptr, 1);
    gemm8_kernel<<<gg, 256, GEMM8_SMEM>>>(pxh, pxl, psx, pWh + 2 * 1024 * 256, pWl + 2 * 1024 * 256, psW + 2 * 1024,
                                          pVh, pVl, 2);
    // launch 6: attention (bf16x3)
    attn_kernel<<<dim3(SEQ / 128, BATCH * N_HEADS), 256, ATTN_SMEM>>>(pQ, pK, pVh, pVl, pAf);
    // launch 7: quantize attention output; launch 8: O projection
    quant_kernel<<<M_TOT, 256>>>(pAf, pAh, pAl, psA);
    gemm8_kernel<<<gg, 256, GEMM8_SMEM>>>(pAh, pAl, psA, pWh + 3 * 1024 * 256, pWl + 3 * 1024 * 256, psW + 3 * 1024,
                                          out, nullptr, 0);
}

// round 11
// speedup vs baseline: 1.7753x; 1.7753x over previous
#include <cuda_runtime.h>
#include <cuda_bf16.h>
#include <cstdint>

#define D_MODEL 1024
#define N_HEADS 16
#define HEAD_DIM 64
#define BATCH 4
#define SEQ 2048
#define M_TOT 8192  // BATCH*SEQ

// ---- scratch (device globals per allocation-free rule) ----
__device__ uint2 g_xs[M_TOT * 512];          // x split, interleaved {hi2,lo2} per k-pair
__device__ uint2 g_Ws[4][D_MODEL * 512];     // Wq,Wk,Wv,Wo split (contiguous rows 0..4095)
__device__ uint2 g_Qh[M_TOT * 512];          // Q scatter (B,H,S,32) interleaved
__device__ uint2 g_Kh[M_TOT * 512];          // K scatter
__device__ uint32_t g_Vh[M_TOT * 512];       // V scatter hi plane (B,H,S,32 u32-pairs)
__device__ uint32_t g_Vl[M_TOT * 512];       // V scatter lo plane
__device__ uint2 g_Ah[M_TOT * 512];          // attention out, split, (B,S,D/2)

// ---------- helpers ----------
__device__ __forceinline__ uint2 split2(float f0, float f1) {
    __nv_bfloat16 h0 = __float2bfloat16_rn(f0), h1 = __float2bfloat16_rn(f1);
    float r0 = f0 - __bfloat162float(h0), r1 = f1 - __bfloat162float(h1);
    __nv_bfloat16 l0 = __float2bfloat16_rn(r0), l1 = __float2bfloat16_rn(r1);
    uint2 u;
    u.x = ((uint32_t)__bfloat16_as_ushort(h1) << 16) | __bfloat16_as_ushort(h0);
    u.y = ((uint32_t)__bfloat16_as_ushort(l1) << 16) | __bfloat16_as_ushort(l0);
    return u;
}

__device__ __forceinline__ void mma_bf16(float c[4], uint32_t a0, uint32_t a1, uint32_t a2, uint32_t a3,
                                         uint32_t b0, uint32_t b1) {
    asm volatile(
        "mma.sync.aligned.m16n8k16.row.col.f32.bf16.bf16.f32 "
        "{%0,%1,%2,%3}, {%4,%5,%6,%7}, {%8,%9}, {%0,%1,%2,%3};\n"
        : "+f"(c[0]), "+f"(c[1]), "+f"(c[2]), "+f"(c[3])
        : "r"(a0), "r"(a1), "r"(a2), "r"(a3), "r"(b0), "r"(b1));
}

__device__ __forceinline__ void ldmx4t(uint32_t &b0, uint32_t &b1, uint32_t &b2, uint32_t &b3, uint32_t addr) {
    asm volatile("ldmatrix.sync.aligned.m8n8.x4.trans.shared.b16 {%0,%1,%2,%3}, [%4];"
                 : "=r"(b0), "=r"(b1), "=r"(b2), "=r"(b3)
                 : "r"(addr));
}

__device__ __forceinline__ void cpa8(uint32_t saddr, const void *g) {
    asm volatile("cp.async.ca.shared.global [%0], [%1], 8;\n" ::"r"(saddr), "l"(g));
}
__device__ __forceinline__ void cpa16(uint32_t saddr, const void *g) {
    asm volatile("cp.async.cg.shared.global [%0], [%1], 16;\n" ::"r"(saddr), "l"(g));
}

// ---------- split pass (x): fp32 -> interleaved {hi2,lo2} ----------
__global__ void __launch_bounds__(256) split_kernel(const float *__restrict__ src, uint2 *__restrict__ dst, int npairs) {
    int i = blockIdx.x * 256 + threadIdx.x;
    if (i < npairs) {
        float2 f = *(const float2 *)(src + 2 * (size_t)i);
        dst[i] = split2(f.x, f.y);
    }
}

// ---------- split pass (all 4 W matrices, one launch) ----------
__global__ void __launch_bounds__(256) split_w_kernel(const float *__restrict__ W0, const float *__restrict__ W1,
                                                      const float *__restrict__ W2, const float *__restrict__ W3,
                                                      uint2 *__restrict__ dst) {
    int row = blockIdx.x;  // 0..4095
    const float *W = (row < 1024) ? W0 : (row < 2048) ? W1 : (row < 3072) ? W2 : W3;
    const float2 *src = (const float2 *)(W + (size_t)(row & 1023) * 1024);
    uint2 *d = dst + (size_t)row * 512;
#pragma unroll
    for (int j = threadIdx.x; j < 512; j += 256) {
        float2 f = src[j];
        d[j] = split2(f.x, f.y);
    }
}

// ---------- GEMM: C[m,n] = sum_k A[m,k]*B[n,k], bf16x3, operands pre-split ----------
// mode 0: plain fp32 out (O projection). mode 3: fused QKV routing by gn>>10.
#define LDAU 19  // u64 slots per row (16 data + 3 pad)
#define GEMM_SMEM (2 * 2 * 128 * LDAU * 8)

__global__ void __launch_bounds__(256) gemm_kernel(const uint2 *__restrict__ A, const uint2 *__restrict__ B,
                                                   void *__restrict__ C0, void *__restrict__ C1,
                                                   void *__restrict__ C2, void *__restrict__ C3, int mode) {
    extern __shared__ uint2 smg[];
    uint2 *As = smg;                 // [2][128][LDAU]
    uint2 *Bs = smg + 2 * 128 * LDAU;
    uint32_t smb;
    asm("{ .reg .u64 t; cvta.to.shared.u64 t, %1; cvt.u32.u64 %0, t; }" : "=r"(smb) : "l"(smg));
    const int tid = threadIdx.x, lane = tid & 31, w = tid >> 5;
    const int m0 = blockIdx.y * 128, n0 = blockIdx.x * 128;
    const int wm = (w >> 2) * 64, wn = (w & 3) * 32;
    const int gr = lane >> 2, gc = lane & 3;

    float acc[4][4][4];
#pragma unroll
    for (int i = 0; i < 4; i++)
#pragma unroll
        for (int j = 0; j < 4; j++)
#pragma unroll
            for (int k = 0; k < 4; k++) acc[i][j][k] = 0.f;

    auto load = [&](int kt, int stg) {
        const uint2 *Ag = A + (size_t)m0 * 512 + kt * 16;
        const uint2 *Bg = B + (size_t)n0 * 512 + kt * 16;
        uint32_t Ad = smb + (stg * 128 * LDAU) * 8;
        uint32_t Bd = smb + ((2 + stg) * 128 * LDAU) * 8;
#pragma unroll
        for (int i = 0; i < 4; i++) {
            int id = tid + i * 256;
            int r = id >> 3, c = (id & 7) * 2;
            cpa8(Ad + (r * LDAU + c) * 8, Ag + (size_t)r * 512 + c);
            cpa8(Ad + (r * LDAU + c + 1) * 8, Ag + (size_t)r * 512 + c + 1);
            cpa8(Bd + (r * LDAU + c) * 8, Bg + (size_t)r * 512 + c);
            cpa8(Bd + (r * LDAU + c + 1) * 8, Bg + (size_t)r * 512 + c + 1);
        }
    };

    load(0, 0);
    asm volatile("cp.async.commit_group;\n");

    for (int kt = 0; kt < 32; ++kt) {
        asm volatile("cp.async.wait_group 0;\n");
        __syncthreads();
        if (kt + 1 < 32) {
            load(kt + 1, (kt + 1) & 1);
            asm volatile("cp.async.commit_group;\n");
        }
        const uint2 *Ad = As + (kt & 1) * 128 * LDAU;
        const uint2 *Bd = Bs + (kt & 1) * 128 * LDAU;
#pragma unroll
        for (int ks = 0; ks < 2; ks++) {
            const int so = ks * 8;
            uint32_t ahi[4][4], alo[4][4], bhi[4][2], blo[4][2];
#pragma unroll
            for (int im = 0; im < 4; im++) {
                const uint2 *p = Ad + (wm + im * 16 + gr) * LDAU + so + gc;
                uint2 v0 = p[0], v1 = p[8 * LDAU], v2 = p[4], v3 = p[8 * LDAU + 4];
                ahi[im][0] = v0.x; ahi[im][1] = v1.x; ahi[im][2] = v2.x; ahi[im][3] = v3.x;
                alo[im][0] = v0.y; alo[im][1] = v1.y; alo[im][2] = v2.y; alo[im][3] = v3.y;
            }
#pragma unroll
            for (int in = 0; in < 4; in++) {
                const uint2 *p = Bd + (wn + in * 8 + gr) * LDAU + so + gc;
                uint2 u0 = p[0], u1 = p[4];
                bhi[in][0] = u0.x; bhi[in][1] = u1.x;
                blo[in][0] = u0.y; blo[in][1] = u1.y;
            }
#pragma unroll
            for (int im = 0; im < 4; im++)
#pragma unroll
                for (int in = 0; in < 4; in++) {
                    mma_bf16(acc[im][in], ahi[im][0], ahi[im][1], ahi[im][2], ahi[im][3], bhi[in][0], bhi[in][1]);
                    mma_bf16(acc[im][in], alo[im][0], alo[im][1], alo[im][2], alo[im][3], bhi[in][0], bhi[in][1]);
                    mma_bf16(acc[im][in], ahi[im][0], ahi[im][1], ahi[im][2], ahi[im][3], blo[in][0], blo[in][1]);
                }
        }
        __syncthreads();
    }

#pragma unroll
    for (int im = 0; im < 4; im++)
#pragma unroll
        for (int in = 0; in < 4; in++) {
            int gm = m0 + wm + im * 16 + gr;
            int gn = n0 + wn + in * 8 + gc * 2;
            float c0 = acc[im][in][0], c1 = acc[im][in][1], c2 = acc[im][in][2], c3 = acc[im][in][3];
            if (mode == 0) {
                float *Cf = (float *)C0;
                *(float2 *)(Cf + (size_t)gm * 1024 + gn) = make_float2(c0, c1);
                *(float2 *)(Cf + (size_t)(gm + 8) * 1024 + gn) = make_float2(c2, c3);
            } else {
                // fused QKV routing
                int mat = gn >> 10;     // 0=Q, 1=K, 2=V
                int gnl = gn & 1023;
                int b = gm >> 11, s2 = gm & 2047, h = gnl >> 6, dd = gnl & 63;
                size_t idx = ((size_t)((b << 4) | h) * 2048 + s2) * 32 + (dd >> 1);
                if (mat == 0) {
                    uint2 *dst = (uint2 *)C0 + idx;
                    dst[0] = split2(c0, c1);
                    dst[8 * 32] = split2(c2, c3);
                } else if (mat == 1) {
                    uint2 *dst = (uint2 *)C1 + idx;
                    dst[0] = split2(c0, c1);
                    dst[8 * 32] = split2(c2, c3);
                } else {
                    uint32_t *Vh = (uint32_t *)C2, *Vl = (uint32_t *)C3;
                    uint2 uA = split2(c0, c1);
                    Vh[idx] = uA.x; Vl[idx] = uA.y;
                    uint2 uB = split2(c2, c3);
                    Vh[idx + 8 * 32] = uB.x; Vl[idx + 8 * 32] = uB.y;
                }
            }
        }
}

// ---------- Flash attention: q-tile 128 (8 warps x 16 rows), kv-tile 64 double-buffered ----------
#define LQ 35
#define QS_OFF 0
#define KS_OFF 35840
#define VH_OFF 71680
#define VL_OFF 90112
#define ATTN_SMEM 108544

__global__ void __launch_bounds__(256, 2) attn_kernel(const uint2 *__restrict__ Q, const uint2 *__restrict__ K,
                                                      const uint32_t *__restrict__ Vh,
                                                      const uint32_t *__restrict__ Vl, uint2 *__restrict__ O) {
    extern __shared__ char smab[];
    uint32_t smb;
    asm("{ .reg .u64 t; cvta.to.shared.u64 t, %1; cvt.u32.u64 %0, t; }" : "=r"(smb) : "l"(smab));
    uint2 *Qs = (uint2 *)smab;
    const int tid = threadIdx.x, lane = tid & 31, w = tid >> 5;
    const int qt = (int)gridDim.x - 1 - (int)blockIdx.x;  // long CTAs first
    const int bh = blockIdx.y;
    const int gr = lane >> 2, gc = lane & 3;
    const size_t hb = (size_t)bh * SEQ;
    const uint32_t vrow = ((lane >> 3) & 1) * 8 + (lane & 7);
    const uint32_t vcol = (lane >> 4) * 8;

    {  // Q tile once (plain stores; covered by first barrier)
        const uint2 *Qg = Q + (hb + qt * 128) * 32;
#pragma unroll
        for (int i = 0; i < 16; i++) {
            int id = tid + i * 256;
            int r = id >> 5, c = id & 31;
            Qs[r * LQ + c] = Qg[r * 32 + c];
        }
    }

    auto loadKV = [&](int kt, int s) {
        const uint2 *Kg = K + (hb + kt * 64) * 32;
        const uint32_t kb = smb + KS_OFF + s * 17920;
#pragma unroll
        for (int i = 0; i < 8; i++) {
            int id = tid + i * 256;
            int r = id >> 5, c = id & 31;
            cpa8(kb + (r * LQ + c) * 8, Kg + r * 32 + c);
        }
        const uint32_t *Vhg = Vh + (hb + kt * 64) * 32;
        const uint32_t *Vlg = Vl + (hb + kt * 64) * 32;
        const uint32_t vhb = smb + VH_OFF + s * 9216;
        const uint32_t vlb = smb + VL_OFF + s * 9216;
#pragma unroll
        for (int i = 0; i < 2; i++) {  // 512 ids: 64 rows x 8 chunks of 16B
            int id = tid + i * 256;
            int r = id >> 3, c = id & 7;
            cpa16(vhb + r * 144 + c * 16, Vhg + r * 32 + c * 4);
            cpa16(vlb + r * 144 + c * 16, Vlg + r * 32 + c * 4);
        }
    };

    float accO[8][4];
#pragma unroll
    for (int i = 0; i < 8; i++)
#pragma unroll
        for (int j = 0; j < 4; j++) accO[i][j] = 0.f;
    float m0r = -1e30f, m1r = -1e30f, l0 = 0.f, l1 = 0.f;
    const int qlast = qt * 128 + w * 16 + 15;
    const int nkt = 2 * qt + 2;

    loadKV(0, 0);
    asm volatile("cp.async.commit_group;\n");

    for (int kt = 0; kt < nkt; ++kt) {
        const int s = kt & 1;
        __syncthreads();  // all warps done with buffer s^1 (previous compute)
        if (kt + 1 < nkt) {
            loadKV(kt + 1, s ^ 1);
            asm volatile("cp.async.commit_group;\n");
            asm volatile("cp.async.wait_group 1;\n");  // stage kt complete; kt+1 in flight
        } else {
            asm volatile("cp.async.wait_group 0;\n");
        }
        __syncthreads();  // stage kt visible to all
        if (kt * 64 > qlast) continue;  // warp fully above diagonal

        const uint2 *Ks = (const uint2 *)(smab + KS_OFF + s * 17920);
        const uint32_t vhb = smb + VH_OFF + s * 9216;
        const uint32_t vlb = smb + VL_OFF + s * 9216;

        // S = Q K^T (16 q-rows x 64 kv)
        float sr[8][4];
#pragma unroll
        for (int nt = 0; nt < 8; nt++)
#pragma unroll
            for (int j = 0; j < 4; j++) sr[nt][j] = 0.f;

#pragma unroll
        for (int ks = 0; ks < 4; ks++) {
            const int so = ks * 8;
            const uint2 *ap = Qs + (w * 16 + gr) * LQ + so + gc;
            uint2 a0 = ap[0], a1 = ap[8 * LQ], a2 = ap[4], a3 = ap[8 * LQ + 4];
#pragma unroll
            for (int nt = 0; nt < 8; nt++) {
                const uint2 *bp = Ks + (nt * 8 + gr) * LQ + so + gc;
                uint2 b0 = bp[0], b1 = bp[4];
                mma_bf16(sr[nt], a0.x, a1.x, a2.x, a3.x, b0.x, b1.x);
                mma_bf16(sr[nt], a0.y, a1.y, a2.y, a3.y, b0.x, b1.x);
                mma_bf16(sr[nt], a0.x, a1.x, a2.x, a3.x, b0.y, b1.y);
            }
        }

        // scale + causal mask + row stats
        const bool needm = (kt * 64 + 63) > (qt * 128 + w * 16);
        const int qg0 = qt * 128 + w * 16 + gr;
        float mx0 = -1e30f, mx1 = -1e30f;
#pragma unroll
        for (int nt = 0; nt < 8; nt++) {
            int kg = kt * 64 + nt * 8 + gc * 2;
#pragma unroll
            for (int j = 0; j < 4; j++) {
                float v = sr[nt][j] * 0.125f;
                if (needm && (kg + (j & 1)) > (qg0 + ((j >> 1) << 3))) v = -1e30f;
                sr[nt][j] = v;
            }
            mx0 = fmaxf(mx0, fmaxf(sr[nt][0], sr[nt][1]));
            mx1 = fmaxf(mx1, fmaxf(sr[nt][2], sr[nt][3]));
        }
        mx0 = fmaxf(mx0, __shfl_xor_sync(0xffffffffu, mx0, 1));
        mx0 = fmaxf(mx0, __shfl_xor_sync(0xffffffffu, mx0, 2));
        mx1 = fmaxf(mx1, __shfl_xor_sync(0xffffffffu, mx1, 1));
        mx1 = fmaxf(mx1, __shfl_xor_sync(0xffffffffu, mx1, 2));
        float mn0 = fmaxf(m0r, mx0), mn1 = fmaxf(m1r, mx1);
        float alpha0 = __expf(m0r - mn0), alpha1 = __expf(m1r - mn1);
        m0r = mn0; m1r = mn1;

        float rs0 = 0.f, rs1 = 0.f;
#pragma unroll
        for (int nt = 0; nt < 8; nt++) {
            float p0 = __expf(sr[nt][0] - mn0);
            float p1 = __expf(sr[nt][1] - mn0);
            float p2 = __expf(sr[nt][2] - mn1);
            float p3 = __expf(sr[nt][3] - mn1);
            sr[nt][0] = p0; sr[nt][1] = p1; sr[nt][2] = p2; sr[nt][3] = p3;
            rs0 += p0 + p1;
            rs1 += p2 + p3;
        }
        rs0 += __shfl_xor_sync(0xffffffffu, rs0, 1);
        rs0 += __shfl_xor_sync(0xffffffffu, rs0, 2);
        rs1 += __shfl_xor_sync(0xffffffffu, rs1, 1);
        rs1 += __shfl_xor_sync(0xffffffffu, rs1, 2);
        l0 = l0 * alpha0 + rs0;
        l1 = l1 * alpha1 + rs1;
#pragma unroll
        for (int nt = 0; nt < 8; nt++) {
            accO[nt][0] *= alpha0; accO[nt][1] *= alpha0;
            accO[nt][2] *= alpha1; accO[nt][3] *= alpha1;
        }

        // O += P V   (P split in registers; V B-fragments via ldmatrix.x4.trans on hi/lo planes)
#pragma unroll
        for (int t = 0; t < 4; t++) {
            uint2 u0 = split2(sr[2 * t][0], sr[2 * t][1]);
            uint2 u1 = split2(sr[2 * t][2], sr[2 * t][3]);
            uint2 u2 = split2(sr[2 * t + 1][0], sr[2 * t + 1][1]);
            uint2 u3 = split2(sr[2 * t + 1][2], sr[2 * t + 1][3]);
            const uint32_t rowoff = (t * 16 + vrow) * 144 + vcol * 2;
#pragma unroll
            for (int ntp = 0; ntp < 4; ntp++) {
                uint32_t bh0, bh1, bh2, bh3, bl0, bl1, bl2, bl3;
                ldmx4t(bh0, bh1, bh2, bh3, vhb + rowoff + ntp * 32);
                ldmx4t(bl0, bl1, bl2, bl3, vlb + rowoff + ntp * 32);
                mma_bf16(accO[2 * ntp], u0.x, u1.x, u2.x, u3.x, bh0, bh1);
                mma_bf16(accO[2 * ntp], u0.y, u1.y, u2.y, u3.y, bh0, bh1);
                mma_bf16(accO[2 * ntp], u0.x, u1.x, u2.x, u3.x, bl0, bl1);
                mma_bf16(accO[2 * ntp + 1], u0.x, u1.x, u2.x, u3.x, bh2, bh3);
                mma_bf16(accO[2 * ntp + 1], u0.y, u1.y, u2.y, u3.y, bh2, bh3);
                mma_bf16(accO[2 * ntp + 1], u0.x, u1.x, u2.x, u3.x, bl2, bl3);
            }
        }
    }

    // epilogue: write split interleaved concat layout (B,S,D/2)
    float inv0 = 1.f / l0, inv1 = 1.f / l1;
    int b = bh >> 4, h = bh & 15;
    int q0 = qt * 128 + w * 16 + gr;
#pragma unroll
    for (int nt = 0; nt < 8; nt++) {
        int slot = h * 32 + nt * 4 + gc;
        O[((size_t)(b * SEQ + q0)) * 512 + slot] = split2(accO[nt][0] * inv0, accO[nt][1] * inv0);
        O[((size_t)(b * SEQ + q0 + 8)) * 512 + slot] = split2(accO[nt][2] * inv1, accO[nt][3] * inv1);
    }
}

// ---------- launch ----------
extern "C" void kernel_launch(void *const *d_in, const int *in_sizes, int n_in, void *d_out, int out_size) {
    const float *x = (const float *)d_in[0];
    const float *Wq = (const float *)d_in[1];
    const float *Wk = (const float *)d_in[2];
    const float *Wv = (const float *)d_in[3];
    const float *Wo = (const float *)d_in[4];
    float *out = (float *)d_out;

    uint2 *pxs, *pQ, *pK, *pA, *pW;
    uint32_t *pVh, *pVl;
    cudaGetSymbolAddress((void **)&pxs, g_xs);
    cudaGetSymbolAddress((void **)&pW, g_Ws);
    cudaGetSymbolAddress((void **)&pQ, g_Qh);
    cudaGetSymbolAddress((void **)&pK, g_Kh);
    cudaGetSymbolAddress((void **)&pVh, g_Vh);
    cudaGetSymbolAddress((void **)&pVl, g_Vl);
    cudaGetSymbolAddress((void **)&pA, g_Ah);

    cudaFuncSetAttribute(gemm_kernel, cudaFuncAttributeMaxDynamicSharedMemorySize, GEMM_SMEM);
    cudaFuncSetAttribute(attn_kernel, cudaFuncAttributeMaxDynamicSharedMemorySize, ATTN_SMEM);

    // launch 1: split x; launch 2: split all W
    split_kernel<<<M_TOT * 512 / 256, 256>>>(x, pxs, M_TOT * 512);
    split_w_kernel<<<4096, 256>>>(Wq, Wk, Wv, Wo, pW);
    // launch 3: fused QKV projection (grid.x covers 3072 output cols)
    gemm_kernel<<<dim3(24, 64), 256, GEMM_SMEM>>>(pxs, pW, pQ, pK, pVh, pVl, 3);
    // launch 4: attention (profiled slot)
    attn_kernel<<<dim3(SEQ / 128, BATCH * N_HEADS), 256, ATTN_SMEM>>>(pQ, pK, pVh, pVl, pA);
    // launch 5: O projection
    gemm_kernel<<<dim3(8, 64), 256, GEMM_SMEM>>>(pA, pW + (size_t)3 * D_MODEL * 512, out, nullptr, nullptr, nullptr,
                                                 0);
}

// round 13
// speedup vs baseline: 2.9213x; 1.6455x over previous
#include <cuda_runtime.h>
#include <cuda_fp16.h>
#include <cstdint>

#define D_MODEL 1024
#define N_HEADS 16
#define HEAD_DIM 64
#define BATCH 4
#define SEQ 2048
#define M_TOT 8192  // BATCH*SEQ

// ---- scratch (device globals per allocation-free rule) ----
__device__ uint2 g_xs[M_TOT * 512];           // x split fp16 {hi2,lo2} per k-pair
__device__ uint32_t g_Ws[4 * 1024 * 512];     // W single fp16 plane (rows 0..4095)
__device__ uint2 g_Q[M_TOT * 512];            // Q scatter (B,H,S,32) split fp16
__device__ uint32_t g_K[M_TOT * 512];         // K scatter single fp16 (B,H,S,32 pairs)
__device__ uint32_t g_V[M_TOT * 512];         // V scatter single fp16
__device__ uint2 g_Ah[M_TOT * 512];           // attention out split fp16 (B,S,512)

// ---------- helpers ----------
__device__ __forceinline__ uint32_t pack2h(float f0, float f1) {
    __half2 h = __floats2half2_rn(f0, f1);  // x=f0 (low), y=f1 (high)
    return *(uint32_t *)&h;
}

__device__ __forceinline__ uint2 split2h(float f0, float f1) {
    __half h0 = __float2half_rn(f0), h1 = __float2half_rn(f1);
    float r0 = f0 - __half2float(h0), r1 = f1 - __half2float(h1);
    __half l0 = __float2half_rn(r0), l1 = __float2half_rn(r1);
    uint2 u;
    u.x = ((uint32_t)__half_as_ushort(h1) << 16) | __half_as_ushort(h0);
    u.y = ((uint32_t)__half_as_ushort(l1) << 16) | __half_as_ushort(l0);
    return u;
}

__device__ __forceinline__ void mma_f16(float c[4], uint32_t a0, uint32_t a1, uint32_t a2, uint32_t a3,
                                        uint32_t b0, uint32_t b1) {
    asm volatile(
        "mma.sync.aligned.m16n8k16.row.col.f32.f16.f16.f32 "
        "{%0,%1,%2,%3}, {%4,%5,%6,%7}, {%8,%9}, {%0,%1,%2,%3};\n"
        : "+f"(c[0]), "+f"(c[1]), "+f"(c[2]), "+f"(c[3])
        : "r"(a0), "r"(a1), "r"(a2), "r"(a3), "r"(b0), "r"(b1));
}

__device__ __forceinline__ void ldmx4t(uint32_t &b0, uint32_t &b1, uint32_t &b2, uint32_t &b3, uint32_t addr) {
    asm volatile("ldmatrix.sync.aligned.m8n8.x4.trans.shared.b16 {%0,%1,%2,%3}, [%4];"
                 : "=r"(b0), "=r"(b1), "=r"(b2), "=r"(b3)
                 : "r"(addr));
}

__device__ __forceinline__ void cpa8(uint32_t saddr, const void *g) {
    asm volatile("cp.async.ca.shared.global [%0], [%1], 8;\n" ::"r"(saddr), "l"(g));
}
__device__ __forceinline__ void cpa16(uint32_t saddr, const void *g) {
    asm volatile("cp.async.cg.shared.global [%0], [%1], 16;\n" ::"r"(saddr), "l"(g));
}

// ---------- split pass (x / attn-out): fp32 -> fp16 {hi2,lo2} ----------
__global__ void __launch_bounds__(256) split_kernel(const float *__restrict__ src, uint2 *__restrict__ dst, int npairs) {
    int i = blockIdx.x * 256 + threadIdx.x;
    if (i < npairs) {
        float2 f = *(const float2 *)(src + 2 * (size_t)i);
        dst[i] = split2h(f.x, f.y);
    }
}

// ---------- split pass (all 4 W, single fp16 plane) ----------
__global__ void __launch_bounds__(256) split_w_kernel(const float *__restrict__ W0, const float *__restrict__ W1,
                                                      const float *__restrict__ W2, const float *__restrict__ W3,
                                                      uint32_t *__restrict__ dst) {
    int row = blockIdx.x;  // 0..4095
    const float *W = (row < 1024) ? W0 : (row < 2048) ? W1 : (row < 3072) ? W2 : W3;
    const float2 *src = (const float2 *)(W + (size_t)(row & 1023) * 1024);
    uint32_t *d = dst + (size_t)row * 512;
#pragma unroll
    for (int j = threadIdx.x; j < 512; j += 256) {
        float2 f = src[j];
        d[j] = pack2h(f.x, f.y);
    }
}

// ---------- GEMM: C[m,n] = sum_k A[m,k]*B[n,k], A split fp16 (2 streams), B single fp16 ----------
// mode 0: fp32 out (O projection). mode 3: fused QKV routing by gn>>10.
#define LDAU 19   // A row stride in uint2 (16 data + 3 pad)
#define LDB 20    // B row stride in u32 (16 data + 4 pad) -> conflict-free, 16B aligned
#define A_STG 19456
#define B_OFF 38912
#define B_STG 10240
#define GEMM_SMEM 59392

__global__ void __launch_bounds__(256) gemm_kernel(const uint2 *__restrict__ A, const uint32_t *__restrict__ B,
                                                   void *__restrict__ C0, void *__restrict__ C1,
                                                   void *__restrict__ C2, int mode) {
    extern __shared__ uint2 smg[];
    uint2 *As = smg;
    uint32_t *Bs32 = (uint32_t *)smg + B_OFF / 4;
    uint32_t smb;
    asm("{ .reg .u64 t; cvta.to.shared.u64 t, %1; cvt.u32.u64 %0, t; }" : "=r"(smb) : "l"(smg));
    const int tid = threadIdx.x, lane = tid & 31, w = tid >> 5;
    const int m0 = blockIdx.y * 128, n0 = blockIdx.x * 128;
    const int wm = (w >> 2) * 64, wn = (w & 3) * 32;
    const int gr = lane >> 2, gc = lane & 3;

    float acc[4][4][4];
#pragma unroll
    for (int i = 0; i < 4; i++)
#pragma unroll
        for (int j = 0; j < 4; j++)
#pragma unroll
            for (int k = 0; k < 4; k++) acc[i][j][k] = 0.f;

    auto load = [&](int kt, int stg) {
        const uint2 *Ag = A + (size_t)m0 * 512 + kt * 16;
        uint32_t Ad = smb + stg * A_STG;
#pragma unroll
        for (int i = 0; i < 4; i++) {
            int id = tid + i * 256;
            int r = id >> 3, c = (id & 7) * 2;
            cpa8(Ad + (r * LDAU + c) * 8, Ag + (size_t)r * 512 + c);
            cpa8(Ad + (r * LDAU + c + 1) * 8, Ag + (size_t)r * 512 + c + 1);
        }
        const uint32_t *Bg = B + (size_t)n0 * 512 + kt * 16;
        uint32_t Bd = smb + B_OFF + stg * B_STG;
#pragma unroll
        for (int i = 0; i < 2; i++) {
            int id = tid + i * 256;
            int r = id >> 2, c = (id & 3) * 4;
            cpa16(Bd + (r * LDB + c) * 4, Bg + (size_t)r * 512 + c);
        }
    };

    load(0, 0);
    asm volatile("cp.async.commit_group;\n");

    for (int kt = 0; kt < 32; ++kt) {
        asm volatile("cp.async.wait_group 0;\n");
        __syncthreads();
        if (kt + 1 < 32) {
            load(kt + 1, (kt + 1) & 1);
            asm volatile("cp.async.commit_group;\n");
        }
        const uint2 *Ad = As + (kt & 1) * (A_STG / 8);
        const uint32_t *Bd = Bs32 + (kt & 1) * (B_STG / 4);
#pragma unroll
        for (int ks = 0; ks < 2; ks++) {
            const int so = ks * 8;
            uint32_t ahi[4][4], alo[4][4], bu[4][2];
#pragma unroll
            for (int im = 0; im < 4; im++) {
                const uint2 *p = Ad + (wm + im * 16 + gr) * LDAU + so + gc;
                uint2 v0 = p[0], v1 = p[8 * LDAU], v2 = p[4], v3 = p[8 * LDAU + 4];
                ahi[im][0] = v0.x; ahi[im][1] = v1.x; ahi[im][2] = v2.x; ahi[im][3] = v3.x;
                alo[im][0] = v0.y; alo[im][1] = v1.y; alo[im][2] = v2.y; alo[im][3] = v3.y;
            }
#pragma unroll
            for (int in = 0; in < 4; in++) {
                const uint32_t *p = Bd + (wn + in * 8 + gr) * LDB + so + gc;
                bu[in][0] = p[0];
                bu[in][1] = p[4];
            }
#pragma unroll
            for (int im = 0; im < 4; im++)
#pragma unroll
                for (int in = 0; in < 4; in++) {
                    mma_f16(acc[im][in], ahi[im][0], ahi[im][1], ahi[im][2], ahi[im][3], bu[in][0], bu[in][1]);
                    mma_f16(acc[im][in], alo[im][0], alo[im][1], alo[im][2], alo[im][3], bu[in][0], bu[in][1]);
                }
        }
        __syncthreads();
    }

#pragma unroll
    for (int im = 0; im < 4; im++)
#pragma unroll
        for (int in = 0; in < 4; in++) {
            int gm = m0 + wm + im * 16 + gr;
            int gn = n0 + wn + in * 8 + gc * 2;
            float c0 = acc[im][in][0], c1 = acc[im][in][1], c2 = acc[im][in][2], c3 = acc[im][in][3];
            if (mode == 0) {
                float *Cf = (float *)C0;
                *(float2 *)(Cf + (size_t)gm * 1024 + gn) = make_float2(c0, c1);
                *(float2 *)(Cf + (size_t)(gm + 8) * 1024 + gn) = make_float2(c2, c3);
            } else {
                int mat = gn >> 10;  // 0=Q, 1=K, 2=V
                int gnl = gn & 1023;
                int b = gm >> 11, s2 = gm & 2047, h = gnl >> 6, dd = gnl & 63;
                size_t idx = ((size_t)((b << 4) | h) * 2048 + s2) * 32 + (dd >> 1);
                if (mat == 0) {
                    uint2 *dst = (uint2 *)C0 + idx;
                    dst[0] = split2h(c0, c1);
                    dst[8 * 32] = split2h(c2, c3);
                } else if (mat == 1) {
                    uint32_t *Kp = (uint32_t *)C1;
                    Kp[idx] = pack2h(c0, c1);
                    Kp[idx + 8 * 32] = pack2h(c2, c3);
                } else {
                    uint32_t *Vp = (uint32_t *)C2;
                    Vp[idx] = pack2h(c0, c1);
                    Vp[idx + 8 * 32] = pack2h(c2, c3);
                }
            }
        }
}

// ---------- Flash attention: Q split fp16 (2-mma QK), K/V/P single fp16 (1-mma PV) ----------
#define LQ 35
#define LK 36  // K row stride in u32 (32 data + 4 pad) -> conflict-free
// smem (bytes): Qs [128][35] uint2 @0 (35840); Ks[2][64][36 u32] @35840 (2x9216);
// Vs[2][64 rows][144B] @54272 (2x9216). total 72704.
#define KS_OFF 35840
#define VS_OFF 54272
#define ATTN_SMEM 72704

__global__ void __launch_bounds__(256, 2) attn_kernel(const uint2 *__restrict__ Q, const uint32_t *__restrict__ K,
                                                      const uint32_t *__restrict__ V, uint2 *__restrict__ O) {
    extern __shared__ char smab[];
    uint32_t smb;
    asm("{ .reg .u64 t; cvta.to.shared.u64 t, %1; cvt.u32.u64 %0, t; }" : "=r"(smb) : "l"(smab));
    uint2 *Qs = (uint2 *)smab;
    const int tid = threadIdx.x, lane = tid & 31, w = tid >> 5;
    const int qt = (int)gridDim.x - 1 - (int)blockIdx.x;  // long CTAs first
    const int bh = blockIdx.y;
    const int gr = lane >> 2, gc = lane & 3;
    const size_t hb = (size_t)bh * SEQ;
    const uint32_t vrow = ((lane >> 3) & 1) * 8 + (lane & 7);
    const uint32_t vcol = (lane >> 4) * 8;

    {  // Q tile once
        const uint2 *Qg = Q + (hb + qt * 128) * 32;
#pragma unroll
        for (int i = 0; i < 16; i++) {
            int id = tid + i * 256;
            int r = id >> 5, c = id & 31;
            Qs[r * LQ + c] = Qg[r * 32 + c];
        }
    }

    auto loadKV = [&](int kt, int s) {
        const uint32_t *Kg = K + (hb + kt * 64) * 32;
        const uint32_t kb = smb + KS_OFF + s * 9216;
#pragma unroll
        for (int i = 0; i < 2; i++) {  // 512 ids: 64 rows x 8 chunks of 16B (32 u32/row)
            int id = tid + i * 256;
            int r = id >> 3, c = (id & 7) * 4;
            cpa16(kb + (r * LK + c) * 4, Kg + r * 32 + c);
        }
        const uint32_t *Vg = V + (hb + kt * 64) * 32;
        const uint32_t vb = smb + VS_OFF + s * 9216;
#pragma unroll
        for (int i = 0; i < 2; i++) {  // 512 ids: 64 rows x 8 chunks of 16B
            int id = tid + i * 256;
            int r = id >> 3, c = id & 7;
            cpa16(vb + r * 144 + c * 16, Vg + r * 32 + c * 4);
        }
    };

    float accO[8][4];
#pragma unroll
    for (int i = 0; i < 8; i++)
#pragma unroll
        for (int j = 0; j < 4; j++) accO[i][j] = 0.f;
    float m0r = -1e30f, m1r = -1e30f, l0 = 0.f, l1 = 0.f;
    const int qlast = qt * 128 + w * 16 + 15;
    const int nkt = 2 * qt + 2;

    loadKV(0, 0);
    asm volatile("cp.async.commit_group;\n");

    for (int kt = 0; kt < nkt; ++kt) {
        const int s = kt & 1;
        __syncthreads();  // all warps done with buffer s^1
        if (kt + 1 < nkt) {
            loadKV(kt + 1, s ^ 1);
            asm volatile("cp.async.commit_group;\n");
            asm volatile("cp.async.wait_group 1;\n");
        } else {
            asm volatile("cp.async.wait_group 0;\n");
        }
        __syncthreads();  // stage kt visible
        if (kt * 64 > qlast) continue;

        const uint32_t *Ks32 = (const uint32_t *)(smab + KS_OFF + s * 9216);
        const uint32_t vb = smb + VS_OFF + s * 9216;

        // S = Q K^T (16 q-rows x 64 kv): Q split (2 mma), K single
        float sr[8][4];
#pragma unroll
        for (int nt = 0; nt < 8; nt++)
#pragma unroll
            for (int j = 0; j < 4; j++) sr[nt][j] = 0.f;

#pragma unroll
        for (int ks = 0; ks < 4; ks++) {
            const int so = ks * 8;
            const uint2 *ap = Qs + (w * 16 + gr) * LQ + so + gc;
            uint2 a0 = ap[0], a1 = ap[8 * LQ], a2 = ap[4], a3 = ap[8 * LQ + 4];
#pragma unroll
            for (int nt = 0; nt < 8; nt++) {
                const uint32_t *bp = Ks32 + (nt * 8 + gr) * LK + so + gc;
                uint32_t b0 = bp[0], b1 = bp[4];
                mma_f16(sr[nt], a0.x, a1.x, a2.x, a3.x, b0, b1);
                mma_f16(sr[nt], a0.y, a1.y, a2.y, a3.y, b0, b1);
            }
        }

        // scale + causal mask + row stats
        const bool needm = (kt * 64 + 63) > (qt * 128 + w * 16);
        const int qg0 = qt * 128 + w * 16 + gr;
        float mx0 = -1e30f, mx1 = -1e30f;
#pragma unroll
        for (int nt = 0; nt < 8; nt++) {
            int kg = kt * 64 + nt * 8 + gc * 2;
#pragma unroll
            for (int j = 0; j < 4; j++) {
                float v = sr[nt][j] * 0.125f;
                if (needm && (kg + (j & 1)) > (qg0 + ((j >> 1) << 3))) v = -1e30f;
                sr[nt][j] = v;
            }
            mx0 = fmaxf(mx0, fmaxf(sr[nt][0], sr[nt][1]));
            mx1 = fmaxf(mx1, fmaxf(sr[nt][2], sr[nt][3]));
        }
        mx0 = fmaxf(mx0, __shfl_xor_sync(0xffffffffu, mx0, 1));
        mx0 = fmaxf(mx0, __shfl_xor_sync(0xffffffffu, mx0, 2));
        mx1 = fmaxf(mx1, __shfl_xor_sync(0xffffffffu, mx1, 1));
        mx1 = fmaxf(mx1, __shfl_xor_sync(0xffffffffu, mx1, 2));
        float mn0 = fmaxf(m0r, mx0), mn1 = fmaxf(m1r, mx1);
        float alpha0 = __expf(m0r - mn0), alpha1 = __expf(m1r - mn1);
        m0r = mn0; m1r = mn1;

        float rs0 = 0.f, rs1 = 0.f;
#pragma unroll
        for (int nt = 0; nt < 8; nt++) {
            float p0 = __expf(sr[nt][0] - mn0);
            float p1 = __expf(sr[nt][1] - mn0);
            float p2 = __expf(sr[nt][2] - mn1);
            float p3 = __expf(sr[nt][3] - mn1);
            sr[nt][0] = p0; sr[nt][1] = p1; sr[nt][2] = p2; sr[nt][3] = p3;
            rs0 += p0 + p1;
            rs1 += p2 + p3;
        }
        rs0 += __shfl_xor_sync(0xffffffffu, rs0, 1);
        rs0 += __shfl_xor_sync(0xffffffffu, rs0, 2);
        rs1 += __shfl_xor_sync(0xffffffffu, rs1, 1);
        rs1 += __shfl_xor_sync(0xffffffffu, rs1, 2);
        l0 = l0 * alpha0 + rs0;
        l1 = l1 * alpha1 + rs1;
#pragma unroll
        for (int nt = 0; nt < 8; nt++) {
            accO[nt][0] *= alpha0; accO[nt][1] *= alpha0;
            accO[nt][2] *= alpha1; accO[nt][3] *= alpha1;
        }

        // O += P V  (P single fp16 in regs; V single fp16 via ldmatrix.x4.trans -> 1 mma per frag)
#pragma unroll
        for (int t = 0; t < 4; t++) {
            uint32_t u0 = pack2h(sr[2 * t][0], sr[2 * t][1]);
            uint32_t u1 = pack2h(sr[2 * t][2], sr[2 * t][3]);
            uint32_t u2 = pack2h(sr[2 * t + 1][0], sr[2 * t + 1][1]);
            uint32_t u3 = pack2h(sr[2 * t + 1][2], sr[2 * t + 1][3]);
            const uint32_t rowoff = (t * 16 + vrow) * 144 + vcol * 2;
#pragma unroll
            for (int ntp = 0; ntp < 4; ntp++) {
                uint32_t bh0, bh1, bh2, bh3;
                ldmx4t(bh0, bh1, bh2, bh3, vb + rowoff + ntp * 32);
                mma_f16(accO[2 * ntp], u0, u1, u2, u3, bh0, bh1);
                mma_f16(accO[2 * ntp + 1], u0, u1, u2, u3, bh2, bh3);
            }
        }
    }

    // epilogue: write split fp16 concat layout (B,S,512)
    float inv0 = 1.f / l0, inv1 = 1.f / l1;
    int b = bh >> 4, h = bh & 15;
    int q0 = qt * 128 + w * 16 + gr;
#pragma unroll
    for (int nt = 0; nt < 8; nt++) {
        int slot = h * 32 + nt * 4 + gc;
        O[((size_t)(b * SEQ + q0)) * 512 + slot] = split2h(accO[nt][0] * inv0, accO[nt][1] * inv0);
        O[((size_t)(b * SEQ + q0 + 8)) * 512 + slot] = split2h(accO[nt][2] * inv1, accO[nt][3] * inv1);
    }
}

// ---------- launch ----------
extern "C" void kernel_launch(void *const *d_in, const int *in_sizes, int n_in, void *d_out, int out_size) {
    const float *x = (const float *)d_in[0];
    const float *Wq = (const float *)d_in[1];
    const float *Wk = (const float *)d_in[2];
    const float *Wv = (const float *)d_in[3];
    const float *Wo = (const float *)d_in[4];
    float *out = (float *)d_out;

    uint2 *pxs, *pQ, *pA;
    uint32_t *pW, *pK, *pV;
    cudaGetSymbolAddress((void **)&pxs, g_xs);
    cudaGetSymbolAddress((void **)&pW, g_Ws);
    cudaGetSymbolAddress((void **)&pQ, g_Q);
    cudaGetSymbolAddress((void **)&pK, g_K);
    cudaGetSymbolAddress((void **)&pV, g_V);
    cudaGetSymbolAddress((void **)&pA, g_Ah);

    cudaFuncSetAttribute(gemm_kernel, cudaFuncAttributeMaxDynamicSharedMemorySize, GEMM_SMEM);
    cudaFuncSetAttribute(attn_kernel, cudaFuncAttributeMaxDynamicSharedMemorySize, ATTN_SMEM);

    // launch 1: split x; launch 2: split all W
    split_kernel<<<M_TOT * 512 / 256, 256>>>(x, pxs, M_TOT * 512);
    split_w_kernel<<<4096, 256>>>(Wq, Wk, Wv, Wo, pW);
    // launch 3: fused QKV projection
    gemm_kernel<<<dim3(24, 64), 256, GEMM_SMEM>>>(pxs, pW, pQ, pK, pV, 3);
    // launch 4: attention (profiled slot)
    attn_kernel<<<dim3(SEQ / 128, BATCH * N_HEADS), 256, ATTN_SMEM>>>(pQ, pK, pV, pA);
    // launch 5: O projection
    gemm_kernel<<<dim3(8, 64), 256, GEMM_SMEM>>>(pA, pW + (size_t)3 * 1024 * 512, out, nullptr, nullptr, 0);
}

// round 14
// speedup vs baseline: 3.2400x; 1.1091x over previous
#include <cuda_runtime.h>
#include <cuda_fp16.h>
#include <cstdint>

#define D_MODEL 1024
#define N_HEADS 16
#define HEAD_DIM 64
#define BATCH 4
#define SEQ 2048
#define M_TOT 8192  // BATCH*SEQ

// ---- scratch (device globals per allocation-free rule) ----
__device__ uint2 g_xs[M_TOT * 512];           // x split fp16 {hi2,lo2} per k-pair
__device__ uint32_t g_Ws[4 * 1024 * 512];     // W single fp16 plane (rows 0..4095)
__device__ uint2 g_Q[M_TOT * 512];            // Q scatter (B,H,S,32) split fp16, pre-scaled by 0.125
__device__ uint32_t g_K[M_TOT * 512];         // K scatter single fp16 (B,H,S,32 pairs)
__device__ uint32_t g_V[M_TOT * 512];         // V scatter single fp16
__device__ uint32_t g_A1[M_TOT * 512];        // attention out single fp16 plane (B,S,512)

// ---------- helpers ----------
__device__ __forceinline__ uint32_t pack2h(float f0, float f1) {
    __half2 h = __floats2half2_rn(f0, f1);
    return *(uint32_t *)&h;
}

__device__ __forceinline__ uint2 split2h(float f0, float f1) {
    __half h0 = __float2half_rn(f0), h1 = __float2half_rn(f1);
    float r0 = f0 - __half2float(h0), r1 = f1 - __half2float(h1);
    __half l0 = __float2half_rn(r0), l1 = __float2half_rn(r1);
    uint2 u;
    u.x = ((uint32_t)__half_as_ushort(h1) << 16) | __half_as_ushort(h0);
    u.y = ((uint32_t)__half_as_ushort(l1) << 16) | __half_as_ushort(l0);
    return u;
}

__device__ __forceinline__ void mma_f16(float c[4], uint32_t a0, uint32_t a1, uint32_t a2, uint32_t a3,
                                        uint32_t b0, uint32_t b1) {
    asm volatile(
        "mma.sync.aligned.m16n8k16.row.col.f32.f16.f16.f32 "
        "{%0,%1,%2,%3}, {%4,%5,%6,%7}, {%8,%9}, {%0,%1,%2,%3};\n"
        : "+f"(c[0]), "+f"(c[1]), "+f"(c[2]), "+f"(c[3])
        : "r"(a0), "r"(a1), "r"(a2), "r"(a3), "r"(b0), "r"(b1));
}

__device__ __forceinline__ void ldmx4(uint32_t &b0, uint32_t &b1, uint32_t &b2, uint32_t &b3, uint32_t addr) {
    asm volatile("ldmatrix.sync.aligned.m8n8.x4.shared.b16 {%0,%1,%2,%3}, [%4];"
                 : "=r"(b0), "=r"(b1), "=r"(b2), "=r"(b3)
                 : "r"(addr));
}

__device__ __forceinline__ void ldmx4t(uint32_t &b0, uint32_t &b1, uint32_t &b2, uint32_t &b3, uint32_t addr) {
    asm volatile("ldmatrix.sync.aligned.m8n8.x4.trans.shared.b16 {%0,%1,%2,%3}, [%4];"
                 : "=r"(b0), "=r"(b1), "=r"(b2), "=r"(b3)
                 : "r"(addr));
}

__device__ __forceinline__ void cpa8(uint32_t saddr, const void *g) {
    asm volatile("cp.async.ca.shared.global [%0], [%1], 8;\n" ::"r"(saddr), "l"(g));
}
__device__ __forceinline__ void cpa16(uint32_t saddr, const void *g) {
    asm volatile("cp.async.cg.shared.global [%0], [%1], 16;\n" ::"r"(saddr), "l"(g));
}

// ---------- split pass (x): fp32 -> fp16 {hi2,lo2} ----------
__global__ void __launch_bounds__(256) split_kernel(const float *__restrict__ src, uint2 *__restrict__ dst, int npairs) {
    int i = blockIdx.x * 256 + threadIdx.x;
    if (i < npairs) {
        float2 f = *(const float2 *)(src + 2 * (size_t)i);
        dst[i] = split2h(f.x, f.y);
    }
}

// ---------- split pass (all 4 W, single fp16 plane) ----------
__global__ void __launch_bounds__(256) split_w_kernel(const float *__restrict__ W0, const float *__restrict__ W1,
                                                      const float *__restrict__ W2, const float *__restrict__ W3,
                                                      uint32_t *__restrict__ dst) {
    int row = blockIdx.x;  // 0..4095
    const float *W = (row < 1024) ? W0 : (row < 2048) ? W1 : (row < 3072) ? W2 : W3;
    const float2 *src = (const float2 *)(W + (size_t)(row & 1023) * 1024);
    uint32_t *d = dst + (size_t)row * 512;
#pragma unroll
    for (int j = threadIdx.x; j < 512; j += 256) {
        float2 f = src[j];
        d[j] = pack2h(f.x, f.y);
    }
}

// ---------- GEMM (QKV): A split fp16 (2 streams), B single fp16; fused QKV routing ----------
#define LDAU 19   // A row stride in uint2
#define LDB 20    // B row stride in u32
#define A_STG 19456
#define B_OFF 38912
#define B_STG 10240
#define GEMM_SMEM 59392

__global__ void __launch_bounds__(256) gemm_kernel(const uint2 *__restrict__ A, const uint32_t *__restrict__ B,
                                                   void *__restrict__ C0, void *__restrict__ C1,
                                                   void *__restrict__ C2) {
    extern __shared__ uint2 smg[];
    uint2 *As = smg;
    uint32_t *Bs32 = (uint32_t *)smg + B_OFF / 4;
    uint32_t smb;
    asm("{ .reg .u64 t; cvta.to.shared.u64 t, %1; cvt.u32.u64 %0, t; }" : "=r"(smb) : "l"(smg));
    const int tid = threadIdx.x, lane = tid & 31, w = tid >> 5;
    const int m0 = blockIdx.y * 128, n0 = blockIdx.x * 128;
    const int wm = (w >> 2) * 64, wn = (w & 3) * 32;
    const int gr = lane >> 2, gc = lane & 3;

    float acc[4][4][4];
#pragma unroll
    for (int i = 0; i < 4; i++)
#pragma unroll
        for (int j = 0; j < 4; j++)
#pragma unroll
            for (int k = 0; k < 4; k++) acc[i][j][k] = 0.f;

    auto load = [&](int kt, int stg) {
        const uint2 *Ag = A + (size_t)m0 * 512 + kt * 16;
        uint32_t Ad = smb + stg * A_STG;
#pragma unroll
        for (int i = 0; i < 4; i++) {
            int id = tid + i * 256;
            int r = id >> 3, c = (id & 7) * 2;
            cpa8(Ad + (r * LDAU + c) * 8, Ag + (size_t)r * 512 + c);
            cpa8(Ad + (r * LDAU + c + 1) * 8, Ag + (size_t)r * 512 + c + 1);
        }
        const uint32_t *Bg = B + (size_t)n0 * 512 + kt * 16;
        uint32_t Bd = smb + B_OFF + stg * B_STG;
#pragma unroll
        for (int i = 0; i < 2; i++) {
            int id = tid + i * 256;
            int r = id >> 2, c = (id & 3) * 4;
            cpa16(Bd + (r * LDB + c) * 4, Bg + (size_t)r * 512 + c);
        }
    };

    load(0, 0);
    asm volatile("cp.async.commit_group;\n");

    for (int kt = 0; kt < 32; ++kt) {
        asm volatile("cp.async.wait_group 0;\n");
        __syncthreads();
        if (kt + 1 < 32) {
            load(kt + 1, (kt + 1) & 1);
            asm volatile("cp.async.commit_group;\n");
        }
        const uint2 *Ad = As + (kt & 1) * (A_STG / 8);
        const uint32_t *Bd = Bs32 + (kt & 1) * (B_STG / 4);
#pragma unroll
        for (int ks = 0; ks < 2; ks++) {
            const int so = ks * 8;
            uint32_t ahi[4][4], alo[4][4], bu[4][2];
#pragma unroll
            for (int im = 0; im < 4; im++) {
                const uint2 *p = Ad + (wm + im * 16 + gr) * LDAU + so + gc;
                uint2 v0 = p[0], v1 = p[8 * LDAU], v2 = p[4], v3 = p[8 * LDAU + 4];
                ahi[im][0] = v0.x; ahi[im][1] = v1.x; ahi[im][2] = v2.x; ahi[im][3] = v3.x;
                alo[im][0] = v0.y; alo[im][1] = v1.y; alo[im][2] = v2.y; alo[im][3] = v3.y;
            }
#pragma unroll
            for (int in = 0; in < 4; in++) {
                const uint32_t *p = Bd + (wn + in * 8 + gr) * LDB + so + gc;
                bu[in][0] = p[0];
                bu[in][1] = p[4];
            }
#pragma unroll
            for (int im = 0; im < 4; im++)
#pragma unroll
                for (int in = 0; in < 4; in++) {
                    mma_f16(acc[im][in], ahi[im][0], ahi[im][1], ahi[im][2], ahi[im][3], bu[in][0], bu[in][1]);
                    mma_f16(acc[im][in], alo[im][0], alo[im][1], alo[im][2], alo[im][3], bu[in][0], bu[in][1]);
                }
        }
        __syncthreads();
    }

#pragma unroll
    for (int im = 0; im < 4; im++)
#pragma unroll
        for (int in = 0; in < 4; in++) {
            int gm = m0 + wm + im * 16 + gr;
            int gn = n0 + wn + in * 8 + gc * 2;
            float c0 = acc[im][in][0], c1 = acc[im][in][1], c2 = acc[im][in][2], c3 = acc[im][in][3];
            int mat = gn >> 10;  // 0=Q, 1=K, 2=V
            int gnl = gn & 1023;
            int b = gm >> 11, s2 = gm & 2047, h = gnl >> 6, dd = gnl & 63;
            size_t idx = ((size_t)((b << 4) | h) * 2048 + s2) * 32 + (dd >> 1);
            if (mat == 0) {
                // Q: fold softmax scale 1/sqrt(64) = 0.125 (exact)
                uint2 *dst = (uint2 *)C0 + idx;
                dst[0] = split2h(c0 * 0.125f, c1 * 0.125f);
                dst[8 * 32] = split2h(c2 * 0.125f, c3 * 0.125f);
            } else if (mat == 1) {
                uint32_t *Kp = (uint32_t *)C1;
                Kp[idx] = pack2h(c0, c1);
                Kp[idx + 8 * 32] = pack2h(c2, c3);
            } else {
                uint32_t *Vp = (uint32_t *)C2;
                Vp[idx] = pack2h(c0, c1);
                Vp[idx + 8 * 32] = pack2h(c2, c3);
            }
        }
}

// ---------- GEMM1 (O-proj): A single fp16, B single fp16, 1 mma/frag, fp32 out ----------
#define G1_STG 10240  // 128 rows x 20 u32 x 4B
#define GEMM1_SMEM (4 * G1_STG)

__global__ void __launch_bounds__(256) gemm1_kernel(const uint32_t *__restrict__ A, const uint32_t *__restrict__ B,
                                                    float *__restrict__ C) {
    extern __shared__ uint32_t smg1[];
    uint32_t smb;
    asm("{ .reg .u64 t; cvta.to.shared.u64 t, %1; cvt.u32.u64 %0, t; }" : "=r"(smb) : "l"(smg1));
    const int tid = threadIdx.x, lane = tid & 31, w = tid >> 5;
    const int m0 = blockIdx.y * 128, n0 = blockIdx.x * 128;
    const int wm = (w >> 2) * 64, wn = (w & 3) * 32;
    const int gr = lane >> 2, gc = lane & 3;

    float acc[4][4][4];
#pragma unroll
    for (int i = 0; i < 4; i++)
#pragma unroll
        for (int j = 0; j < 4; j++)
#pragma unroll
            for (int k = 0; k < 4; k++) acc[i][j][k] = 0.f;

    auto load = [&](int kt, int stg) {
        const uint32_t *Ag = A + (size_t)m0 * 512 + kt * 16;
        const uint32_t *Bg = B + (size_t)n0 * 512 + kt * 16;
        uint32_t Ad = smb + stg * 2 * G1_STG;
        uint32_t Bd = Ad + G1_STG;
#pragma unroll
        for (int i = 0; i < 2; i++) {
            int id = tid + i * 256;
            int r = id >> 2, c = (id & 3) * 4;
            cpa16(Ad + (r * LDB + c) * 4, Ag + (size_t)r * 512 + c);
            cpa16(Bd + (r * LDB + c) * 4, Bg + (size_t)r * 512 + c);
        }
    };

    load(0, 0);
    asm volatile("cp.async.commit_group;\n");

    for (int kt = 0; kt < 32; ++kt) {
        asm volatile("cp.async.wait_group 0;\n");
        __syncthreads();
        if (kt + 1 < 32) {
            load(kt + 1, (kt + 1) & 1);
            asm volatile("cp.async.commit_group;\n");
        }
        const uint32_t *Ad = smg1 + (kt & 1) * 2 * (G1_STG / 4);
        const uint32_t *Bd = Ad + G1_STG / 4;
#pragma unroll
        for (int ks = 0; ks < 2; ks++) {
            const int so = ks * 8;
            uint32_t au[4][4], bu[4][2];
#pragma unroll
            for (int im = 0; im < 4; im++) {
                const uint32_t *p = Ad + (wm + im * 16 + gr) * LDB + so + gc;
                au[im][0] = p[0]; au[im][1] = p[8 * LDB];
                au[im][2] = p[4]; au[im][3] = p[8 * LDB + 4];
            }
#pragma unroll
            for (int in = 0; in < 4; in++) {
                const uint32_t *p = Bd + (wn + in * 8 + gr) * LDB + so + gc;
                bu[in][0] = p[0];
                bu[in][1] = p[4];
            }
#pragma unroll
            for (int im = 0; im < 4; im++)
#pragma unroll
                for (int in = 0; in < 4; in++)
                    mma_f16(acc[im][in], au[im][0], au[im][1], au[im][2], au[im][3], bu[in][0], bu[in][1]);
        }
        __syncthreads();
    }

#pragma unroll
    for (int im = 0; im < 4; im++)
#pragma unroll
        for (int in = 0; in < 4; in++) {
            int gm = m0 + wm + im * 16 + gr;
            int gn = n0 + wn + in * 8 + gc * 2;
            *(float2 *)(C + (size_t)gm * 1024 + gn) = make_float2(acc[im][in][0], acc[im][in][1]);
            *(float2 *)(C + (size_t)(gm + 8) * 1024 + gn) = make_float2(acc[im][in][2], acc[im][in][3]);
        }
}

// ---------- Flash attention: Q split (2-mma QK via ldmatrix K), K/V/P single (1-mma PV) ----------
#define LQ 35
#define LKB 144  // K/V row stride in bytes
#define KS_OFF 35840
#define VS_OFF 54272
#define ATTN_SMEM 72704

__global__ void __launch_bounds__(256, 2) attn_kernel(const uint2 *__restrict__ Q, const uint32_t *__restrict__ K,
                                                      const uint32_t *__restrict__ V, uint32_t *__restrict__ O) {
    extern __shared__ char smab[];
    uint32_t smb;
    asm("{ .reg .u64 t; cvta.to.shared.u64 t, %1; cvt.u32.u64 %0, t; }" : "=r"(smb) : "l"(smab));
    uint2 *Qs = (uint2 *)smab;
    const int tid = threadIdx.x, lane = tid & 31, w = tid >> 5;
    const int qt = (int)gridDim.x - 1 - (int)blockIdx.x;  // long CTAs first
    const int bh = blockIdx.y;
    const int gr = lane >> 2, gc = lane & 3;
    const size_t hb = (size_t)bh * SEQ;
    // V ldmatrix.trans lane addressing (rows = kv, within 16-row block)
    const uint32_t vrow = ((lane >> 3) & 1) * 8 + (lane & 7);
    const uint32_t vcol = (lane >> 4) * 8;
    // K ldmatrix (non-trans) lane addressing: tiles (ntEven kLo, ntEven kHi, ntOdd kLo, ntOdd kHi)
    const uint32_t krow = ((lane >> 4) << 3) + (lane & 7);          // row within 16-row nt-pair block
    const uint32_t koff = krow * LKB + (((lane >> 3) & 1) << 4);    // + k-half 16B

    {  // Q tile once
        const uint2 *Qg = Q + (hb + qt * 128) * 32;
#pragma unroll
        for (int i = 0; i < 16; i++) {
            int id = tid + i * 256;
            int r = id >> 5, c = id & 31;
            Qs[r * LQ + c] = Qg[r * 32 + c];
        }
    }

    auto loadKV = [&](int kt, int s) {
        const uint32_t *Kg = K + (hb + kt * 64) * 32;
        const uint32_t kb = smb + KS_OFF + s * 9216;
#pragma unroll
        for (int i = 0; i < 2; i++) {  // 64 rows x 8 chunks of 16B
            int id = tid + i * 256;
            int r = id >> 3, c = id & 7;
            cpa16(kb + r * LKB + c * 16, Kg + r * 32 + c * 4);
        }
        const uint32_t *Vg = V + (hb + kt * 64) * 32;
        const uint32_t vb = smb + VS_OFF + s * 9216;
#pragma unroll
        for (int i = 0; i < 2; i++) {
            int id = tid + i * 256;
            int r = id >> 3, c = id & 7;
            cpa16(vb + r * LKB + c * 16, Vg + r * 32 + c * 4);
        }
    };

    float accO[8][4];
#pragma unroll
    for (int i = 0; i < 8; i++)
#pragma unroll
        for (int j = 0; j < 4; j++) accO[i][j] = 0.f;
    float m0r = -1e30f, m1r = -1e30f, l0 = 0.f, l1 = 0.f;
    const int qlast = qt * 128 + w * 16 + 15;
    const int nkt = 2 * qt + 2;

    loadKV(0, 0);
    asm volatile("cp.async.commit_group;\n");

    for (int kt = 0; kt < nkt; ++kt) {
        const int s = kt & 1;
        __syncthreads();  // all warps done with buffer s^1
        if (kt + 1 < nkt) {
            loadKV(kt + 1, s ^ 1);
            asm volatile("cp.async.commit_group;\n");
            asm volatile("cp.async.wait_group 1;\n");
        } else {
            asm volatile("cp.async.wait_group 0;\n");
        }
        __syncthreads();  // stage kt visible
        if (kt * 64 > qlast) continue;

        const uint32_t kaddr = smb + KS_OFF + s * 9216 + koff;
        const uint32_t vb = smb + VS_OFF + s * 9216;

        // S = Q K^T (16 q-rows x 64 kv): Q split (2 mma), K via ldmatrix.x4
        float sr[8][4];
#pragma unroll
        for (int nt = 0; nt < 8; nt++)
#pragma unroll
            for (int j = 0; j < 4; j++) sr[nt][j] = 0.f;

#pragma unroll
        for (int ks = 0; ks < 4; ks++) {
            const int so = ks * 8;
            const uint2 *ap = Qs + (w * 16 + gr) * LQ + so + gc;
            uint2 a0 = ap[0], a1 = ap[8 * LQ], a2 = ap[4], a3 = ap[8 * LQ + 4];
            const uint32_t ka = kaddr + ks * 32;
#pragma unroll
            for (int ntp = 0; ntp < 4; ntp++) {
                uint32_t kb0, kb1, kb2, kb3;
                ldmx4(kb0, kb1, kb2, kb3, ka + ntp * (16 * LKB));
                mma_f16(sr[2 * ntp], a0.x, a1.x, a2.x, a3.x, kb0, kb1);
                mma_f16(sr[2 * ntp], a0.y, a1.y, a2.y, a3.y, kb0, kb1);
                mma_f16(sr[2 * ntp + 1], a0.x, a1.x, a2.x, a3.x, kb2, kb3);
                mma_f16(sr[2 * ntp + 1], a0.y, a1.y, a2.y, a3.y, kb2, kb3);
            }
        }

        // causal mask (diagonal tiles only; scale pre-folded into Q) + row stats
        const bool needm = (kt * 64 + 63) > (qt * 128 + w * 16);
        if (needm) {
            const int qg0 = qt * 128 + w * 16 + gr;
#pragma unroll
            for (int nt = 0; nt < 8; nt++) {
                int kg = kt * 64 + nt * 8 + gc * 2;
#pragma unroll
                for (int j = 0; j < 4; j++)
                    if ((kg + (j & 1)) > (qg0 + ((j >> 1) << 3))) sr[nt][j] = -1e30f;
            }
        }
        float mx0 = -1e30f, mx1 = -1e30f;
#pragma unroll
        for (int nt = 0; nt < 8; nt++) {
            mx0 = fmaxf(mx0, fmaxf(sr[nt][0], sr[nt][1]));
            mx1 = fmaxf(mx1, fmaxf(sr[nt][2], sr[nt][3]));
        }
        mx0 = fmaxf(mx0, __shfl_xor_sync(0xffffffffu, mx0, 1));
        mx0 = fmaxf(mx0, __shfl_xor_sync(0xffffffffu, mx0, 2));
        mx1 = fmaxf(mx1, __shfl_xor_sync(0xffffffffu, mx1, 1));
        mx1 = fmaxf(mx1, __shfl_xor_sync(0xffffffffu, mx1, 2));
        float mn0 = fmaxf(m0r, mx0), mn1 = fmaxf(m1r, mx1);
        float alpha0 = __expf(m0r - mn0), alpha1 = __expf(m1r - mn1);
        m0r = mn0; m1r = mn1;

        float rs0 = 0.f, rs1 = 0.f;
#pragma unroll
        for (int nt = 0; nt < 8; nt++) {
            float p0 = __expf(sr[nt][0] - mn0);
            float p1 = __expf(sr[nt][1] - mn0);
            float p2 = __expf(sr[nt][2] - mn1);
            float p3 = __expf(sr[nt][3] - mn1);
            sr[nt][0] = p0; sr[nt][1] = p1; sr[nt][2] = p2; sr[nt][3] = p3;
            rs0 += p0 + p1;
            rs1 += p2 + p3;
        }
        rs0 += __shfl_xor_sync(0xffffffffu, rs0, 1);
        rs0 += __shfl_xor_sync(0xffffffffu, rs0, 2);
        rs1 += __shfl_xor_sync(0xffffffffu, rs1, 1);
        rs1 += __shfl_xor_sync(0xffffffffu, rs1, 2);
        l0 = l0 * alpha0 + rs0;
        l1 = l1 * alpha1 + rs1;
#pragma unroll
        for (int nt = 0; nt < 8; nt++) {
            accO[nt][0] *= alpha0; accO[nt][1] *= alpha0;
            accO[nt][2] *= alpha1; accO[nt][3] *= alpha1;
        }

        // O += P V  (P single fp16; V via ldmatrix.x4.trans)
#pragma unroll
        for (int t = 0; t < 4; t++) {
            uint32_t u0 = pack2h(sr[2 * t][0], sr[2 * t][1]);
            uint32_t u1 = pack2h(sr[2 * t][2], sr[2 * t][3]);
            uint32_t u2 = pack2h(sr[2 * t + 1][0], sr[2 * t + 1][1]);
            uint32_t u3 = pack2h(sr[2 * t + 1][2], sr[2 * t + 1][3]);
            const uint32_t rowoff = (t * 16 + vrow) * LKB + vcol * 2;
#pragma unroll
            for (int ntp = 0; ntp < 4; ntp++) {
                uint32_t bh0, bh1, bh2, bh3;
                ldmx4t(bh0, bh1, bh2, bh3, vb + rowoff + ntp * 32);
                mma_f16(accO[2 * ntp], u0, u1, u2, u3, bh0, bh1);
                mma_f16(accO[2 * ntp + 1], u0, u1, u2, u3, bh2, bh3);
            }
        }
    }

    // epilogue: write single fp16 plane, concat layout (B,S,512)
    float inv0 = 1.f / l0, inv1 = 1.f / l1;
    int b = bh >> 4, h = bh & 15;
    int q0 = qt * 128 + w * 16 + gr;
#pragma unroll
    for (int nt = 0; nt < 8; nt++) {
        int slot = h * 32 + nt * 4 + gc;
        O[((size_t)(b * SEQ + q0)) * 512 + slot] = pack2h(accO[nt][0] * inv0, accO[nt][1] * inv0);
        O[((size_t)(b * SEQ + q0 + 8)) * 512 + slot] = pack2h(accO[nt][2] * inv1, accO[nt][3] * inv1);
    }
}

// ---------- launch ----------
extern "C" void kernel_launch(void *const *d_in, const int *in_sizes, int n_in, void *d_out, int out_size) {
    const float *x = (const float *)d_in[0];
    const float *Wq = (const float *)d_in[1];
    const float *Wk = (const float *)d_in[2];
    const float *Wv = (const float *)d_in[3];
    const float *Wo = (const float *)d_in[4];
    float *out = (float *)d_out;

    uint2 *pxs, *pQ;
    uint32_t *pW, *pK, *pV, *pA1;
    cudaGetSymbolAddress((void **)&pxs, g_xs);
    cudaGetSymbolAddress((void **)&pW, g_Ws);
    cudaGetSymbolAddress((void **)&pQ, g_Q);
    cudaGetSymbolAddress((void **)&pK, g_K);
    cudaGetSymbolAddress((void **)&pV, g_V);
    cudaGetSymbolAddress((void **)&pA1, g_A1);

    cudaFuncSetAttribute(gemm_kernel, cudaFuncAttributeMaxDynamicSharedMemorySize, GEMM_SMEM);
    cudaFuncSetAttribute(gemm1_kernel, cudaFuncAttributeMaxDynamicSharedMemorySize, GEMM1_SMEM);
    cudaFuncSetAttribute(attn_kernel, cudaFuncAttributeMaxDynamicSharedMemorySize, ATTN_SMEM);

    // launch 1: split x; launch 2: split all W
    split_kernel<<<M_TOT * 512 / 256, 256>>>(x, pxs, M_TOT * 512);
    split_w_kernel<<<4096, 256>>>(Wq, Wk, Wv, Wo, pW);
    // launch 3: fused QKV projection
    gemm_kernel<<<dim3(24, 64), 256, GEMM_SMEM>>>(pxs, pW, pQ, pK, pV);
    // launch 4: attention (profiled slot)
    attn_kernel<<<dim3(SEQ / 128, BATCH * N_HEADS), 256, ATTN_SMEM>>>(pQ, pK, pV, pA1);
    // launch 5: O projection (single x single, 1 mma/frag)
    gemm1_kernel<<<dim3(8, 64), 256, GEMM1_SMEM>>>(pA1, pW + (size_t)3 * 1024 * 512, out);
}

// round 15
// speedup vs baseline: 4.2268x; 1.3045x over previous
#include <cuda_runtime.h>
#include <cuda_fp16.h>
#include <cstdint>

#define D_MODEL 1024
#define N_HEADS 16
#define HEAD_DIM 64
#define BATCH 4
#define SEQ 2048
#define M_TOT 8192  // BATCH*SEQ

// ---- scratch (device globals per allocation-free rule) ----
__device__ uint32_t g_x1[M_TOT * 512];        // x single fp16 plane
__device__ uint32_t g_Ws[4 * 1024 * 512];     // W single fp16 plane (rows 0..4095)
__device__ uint2 g_Q[M_TOT * 512];            // Q scatter (B,H,S,32) split fp16, pre-scaled by 0.125
__device__ uint32_t g_K[M_TOT * 512];         // K scatter single fp16 (B,H,S,32 pairs)
__device__ uint32_t g_V[M_TOT * 512];         // V scatter single fp16
__device__ uint32_t g_A1[M_TOT * 512];        // attention out single fp16 plane (B,S,512)

// ---------- helpers ----------
__device__ __forceinline__ uint32_t pack2h(float f0, float f1) {
    __half2 h = __floats2half2_rn(f0, f1);
    return *(uint32_t *)&h;
}

__device__ __forceinline__ uint2 split2h(float f0, float f1) {
    __half h0 = __float2half_rn(f0), h1 = __float2half_rn(f1);
    float r0 = f0 - __half2float(h0), r1 = f1 - __half2float(h1);
    __half l0 = __float2half_rn(r0), l1 = __float2half_rn(r1);
    uint2 u;
    u.x = ((uint32_t)__half_as_ushort(h1) << 16) | __half_as_ushort(h0);
    u.y = ((uint32_t)__half_as_ushort(l1) << 16) | __half_as_ushort(l0);
    return u;
}

__device__ __forceinline__ void mma_f16(float c[4], uint32_t a0, uint32_t a1, uint32_t a2, uint32_t a3,
                                        uint32_t b0, uint32_t b1) {
    asm volatile(
        "mma.sync.aligned.m16n8k16.row.col.f32.f16.f16.f32 "
        "{%0,%1,%2,%3}, {%4,%5,%6,%7}, {%8,%9}, {%0,%1,%2,%3};\n"
        : "+f"(c[0]), "+f"(c[1]), "+f"(c[2]), "+f"(c[3])
        : "r"(a0), "r"(a1), "r"(a2), "r"(a3), "r"(b0), "r"(b1));
}

__device__ __forceinline__ void ldmx4(uint32_t &b0, uint32_t &b1, uint32_t &b2, uint32_t &b3, uint32_t addr) {
    asm volatile("ldmatrix.sync.aligned.m8n8.x4.shared.b16 {%0,%1,%2,%3}, [%4];"
                 : "=r"(b0), "=r"(b1), "=r"(b2), "=r"(b3)
                 : "r"(addr));
}

__device__ __forceinline__ void ldmx4t(uint32_t &b0, uint32_t &b1, uint32_t &b2, uint32_t &b3, uint32_t addr) {
    asm volatile("ldmatrix.sync.aligned.m8n8.x4.trans.shared.b16 {%0,%1,%2,%3}, [%4];"
                 : "=r"(b0), "=r"(b1), "=r"(b2), "=r"(b3)
                 : "r"(addr));
}

__device__ __forceinline__ void cpa16(uint32_t saddr, const void *g) {
    asm volatile("cp.async.cg.shared.global [%0], [%1], 16;\n" ::"r"(saddr), "l"(g));
}

// ---------- pack pass (x): fp32 -> single fp16 plane ----------
__global__ void __launch_bounds__(256) pack_kernel(const float *__restrict__ src, uint32_t *__restrict__ dst,
                                                   int npairs) {
    int i = blockIdx.x * 256 + threadIdx.x;
    if (i < npairs) {
        float2 f = *(const float2 *)(src + 2 * (size_t)i);
        dst[i] = pack2h(f.x, f.y);
    }
}

// ---------- pack pass (all 4 W, single fp16 plane) ----------
__global__ void __launch_bounds__(256) split_w_kernel(const float *__restrict__ W0, const float *__restrict__ W1,
                                                      const float *__restrict__ W2, const float *__restrict__ W3,
                                                      uint32_t *__restrict__ dst) {
    int row = blockIdx.x;  // 0..4095
    const float *W = (row < 1024) ? W0 : (row < 2048) ? W1 : (row < 3072) ? W2 : W3;
    const float2 *src = (const float2 *)(W + (size_t)(row & 1023) * 1024);
    uint32_t *d = dst + (size_t)row * 512;
#pragma unroll
    for (int j = threadIdx.x; j < 512; j += 256) {
        float2 f = src[j];
        d[j] = pack2h(f.x, f.y);
    }
}

#define LDB 20        // smem row stride in u32 (16 data + 4 pad)
#define G_STG 10240   // one plane stage: 128 rows x 20 u32 x 4B
#define GEMM_SMEM (4 * G_STG)

// ---------- GEMM (QKV): single fp16 x single fp16, 1 mma/frag; fused QKV routing ----------
__global__ void __launch_bounds__(256) gemm_qkv_kernel(const uint32_t *__restrict__ A, const uint32_t *__restrict__ B,
                                                       void *__restrict__ C0, void *__restrict__ C1,
                                                       void *__restrict__ C2) {
    extern __shared__ uint32_t smg[];
    uint32_t smb;
    asm("{ .reg .u64 t; cvta.to.shared.u64 t, %1; cvt.u32.u64 %0, t; }" : "=r"(smb) : "l"(smg));
    const int tid = threadIdx.x, lane = tid & 31, w = tid >> 5;
    const int m0 = blockIdx.y * 128, n0 = blockIdx.x * 128;
    const int wm = (w >> 2) * 64, wn = (w & 3) * 32;
    const int gr = lane >> 2, gc = lane & 3;

    float acc[4][4][4];
#pragma unroll
    for (int i = 0; i < 4; i++)
#pragma unroll
        for (int j = 0; j < 4; j++)
#pragma unroll
            for (int k = 0; k < 4; k++) acc[i][j][k] = 0.f;

    auto load = [&](int kt, int stg) {
        const uint32_t *Ag = A + (size_t)m0 * 512 + kt * 16;
        const uint32_t *Bg = B + (size_t)n0 * 512 + kt * 16;
        uint32_t Ad = smb + stg * 2 * G_STG;
        uint32_t Bd = Ad + G_STG;
#pragma unroll
        for (int i = 0; i < 2; i++) {
            int id = tid + i * 256;
            int r = id >> 2, c = (id & 3) * 4;
            cpa16(Ad + (r * LDB + c) * 4, Ag + (size_t)r * 512 + c);
            cpa16(Bd + (r * LDB + c) * 4, Bg + (size_t)r * 512 + c);
        }
    };

    load(0, 0);
    asm volatile("cp.async.commit_group;\n");

    for (int kt = 0; kt < 32; ++kt) {
        asm volatile("cp.async.wait_group 0;\n");
        __syncthreads();
        if (kt + 1 < 32) {
            load(kt + 1, (kt + 1) & 1);
            asm volatile("cp.async.commit_group;\n");
        }
        const uint32_t *Ad = smg + (kt & 1) * 2 * (G_STG / 4);
        const uint32_t *Bd = Ad + G_STG / 4;
#pragma unroll
        for (int ks = 0; ks < 2; ks++) {
            const int so = ks * 8;
            uint32_t au[4][4], bu[4][2];
#pragma unroll
            for (int im = 0; im < 4; im++) {
                const uint32_t *p = Ad + (wm + im * 16 + gr) * LDB + so + gc;
                au[im][0] = p[0]; au[im][1] = p[8 * LDB];
                au[im][2] = p[4]; au[im][3] = p[8 * LDB + 4];
            }
#pragma unroll
            for (int in = 0; in < 4; in++) {
                const uint32_t *p = Bd + (wn + in * 8 + gr) * LDB + so + gc;
                bu[in][0] = p[0];
                bu[in][1] = p[4];
            }
#pragma unroll
            for (int im = 0; im < 4; im++)
#pragma unroll
                for (int in = 0; in < 4; in++)
                    mma_f16(acc[im][in], au[im][0], au[im][1], au[im][2], au[im][3], bu[in][0], bu[in][1]);
        }
        __syncthreads();
    }

#pragma unroll
    for (int im = 0; im < 4; im++)
#pragma unroll
        for (int in = 0; in < 4; in++) {
            int gm = m0 + wm + im * 16 + gr;
            int gn = n0 + wn + in * 8 + gc * 2;
            float c0 = acc[im][in][0], c1 = acc[im][in][1], c2 = acc[im][in][2], c3 = acc[im][in][3];
            int mat = gn >> 10;  // 0=Q, 1=K, 2=V
            int gnl = gn & 1023;
            int b = gm >> 11, s2 = gm & 2047, h = gnl >> 6, dd = gnl & 63;
            size_t idx = ((size_t)((b << 4) | h) * 2048 + s2) * 32 + (dd >> 1);
            if (mat == 0) {
                // Q: fold softmax scale 1/sqrt(64) = 0.125 (exact); keep split for 2-mma QK
                uint2 *dst = (uint2 *)C0 + idx;
                dst[0] = split2h(c0 * 0.125f, c1 * 0.125f);
                dst[8 * 32] = split2h(c2 * 0.125f, c3 * 0.125f);
            } else if (mat == 1) {
                uint32_t *Kp = (uint32_t *)C1;
                Kp[idx] = pack2h(c0, c1);
                Kp[idx + 8 * 32] = pack2h(c2, c3);
            } else {
                uint32_t *Vp = (uint32_t *)C2;
                Vp[idx] = pack2h(c0, c1);
                Vp[idx + 8 * 32] = pack2h(c2, c3);
            }
        }
}

// ---------- GEMM1 (O-proj): single x single, 1 mma/frag, fp32 out ----------
__global__ void __launch_bounds__(256) gemm1_kernel(const uint32_t *__restrict__ A, const uint32_t *__restrict__ B,
                                                    float *__restrict__ C) {
    extern __shared__ uint32_t smg1[];
    uint32_t smb;
    asm("{ .reg .u64 t; cvta.to.shared.u64 t, %1; cvt.u32.u64 %0, t; }" : "=r"(smb) : "l"(smg1));
    const int tid = threadIdx.x, lane = tid & 31, w = tid >> 5;
    const int m0 = blockIdx.y * 128, n0 = blockIdx.x * 128;
    const int wm = (w >> 2) * 64, wn = (w & 3) * 32;
    const int gr = lane >> 2, gc = lane & 3;

    float acc[4][4][4];
#pragma unroll
    for (int i = 0; i < 4; i++)
#pragma unroll
        for (int j = 0; j < 4; j++)
#pragma unroll
            for (int k = 0; k < 4; k++) acc[i][j][k] = 0.f;

    auto load = [&](int kt, int stg) {
        const uint32_t *Ag = A + (size_t)m0 * 512 + kt * 16;
        const uint32_t *Bg = B + (size_t)n0 * 512 + kt * 16;
        uint32_t Ad = smb + stg * 2 * G_STG;
        uint32_t Bd = Ad + G_STG;
#pragma unroll
        for (int i = 0; i < 2; i++) {
            int id = tid + i * 256;
            int r = id >> 2, c = (id & 3) * 4;
            cpa16(Ad + (r * LDB + c) * 4, Ag + (size_t)r * 512 + c);
            cpa16(Bd + (r * LDB + c) * 4, Bg + (size_t)r * 512 + c);
        }
    };

    load(0, 0);
    asm volatile("cp.async.commit_group;\n");

    for (int kt = 0; kt < 32; ++kt) {
        asm volatile("cp.async.wait_group 0;\n");
        __syncthreads();
        if (kt + 1 < 32) {
            load(kt + 1, (kt + 1) & 1);
            asm volatile("cp.async.commit_group;\n");
        }
        const uint32_t *Ad = smg1 + (kt & 1) * 2 * (G_STG / 4);
        const uint32_t *Bd = Ad + G_STG / 4;
#pragma unroll
        for (int ks = 0; ks < 2; ks++) {
            const int so = ks * 8;
            uint32_t au[4][4], bu[4][2];
#pragma unroll
            for (int im = 0; im < 4; im++) {
                const uint32_t *p = Ad + (wm + im * 16 + gr) * LDB + so + gc;
                au[im][0] = p[0]; au[im][1] = p[8 * LDB];
                au[im][2] = p[4]; au[im][3] = p[8 * LDB + 4];
            }
#pragma unroll
            for (int in = 0; in < 4; in++) {
                const uint32_t *p = Bd + (wn + in * 8 + gr) * LDB + so + gc;
                bu[in][0] = p[0];
                bu[in][1] = p[4];
            }
#pragma unroll
            for (int im = 0; im < 4; im++)
#pragma unroll
                for (int in = 0; in < 4; in++)
                    mma_f16(acc[im][in], au[im][0], au[im][1], au[im][2], au[im][3], bu[in][0], bu[in][1]);
        }
        __syncthreads();
    }

#pragma unroll
    for (int im = 0; im < 4; im++)
#pragma unroll
        for (int in = 0; in < 4; in++) {
            int gm = m0 + wm + im * 16 + gr;
            int gn = n0 + wn + in * 8 + gc * 2;
            *(float2 *)(C + (size_t)gm * 1024 + gn) = make_float2(acc[im][in][0], acc[im][in][1]);
            *(float2 *)(C + (size_t)(gm + 8) * 1024 + gn) = make_float2(acc[im][in][2], acc[im][in][3]);
        }
}

// ---------- Flash attention: Q split (2-mma QK via ldmatrix K), K/V/P single (1-mma PV) ----------
#define LQ 35
#define LKB 144  // K/V row stride in bytes
#define KS_OFF 35840
#define VS_OFF 54272
#define ATTN_SMEM 72704

__global__ void __launch_bounds__(256, 2) attn_kernel(const uint2 *__restrict__ Q, const uint32_t *__restrict__ K,
                                                      const uint32_t *__restrict__ V, uint32_t *__restrict__ O) {
    extern __shared__ char smab[];
    uint32_t smb;
    asm("{ .reg .u64 t; cvta.to.shared.u64 t, %1; cvt.u32.u64 %0, t; }" : "=r"(smb) : "l"(smab));
    uint2 *Qs = (uint2 *)smab;
    const int tid = threadIdx.x, lane = tid & 31, w = tid >> 5;
    const int qt = (int)gridDim.x - 1 - (int)blockIdx.x;  // long CTAs first
    const int bh = blockIdx.y;
    const int gr = lane >> 2, gc = lane & 3;
    const size_t hb = (size_t)bh * SEQ;
    const uint32_t vrow = ((lane >> 3) & 1) * 8 + (lane & 7);
    const uint32_t vcol = (lane >> 4) * 8;
    const uint32_t krow = ((lane >> 4) << 3) + (lane & 7);
    const uint32_t koff = krow * LKB + (((lane >> 3) & 1) << 4);

    {  // Q tile once
        const uint2 *Qg = Q + (hb + qt * 128) * 32;
#pragma unroll
        for (int i = 0; i < 16; i++) {
            int id = tid + i * 256;
            int r = id >> 5, c = id & 31;
            Qs[r * LQ + c] = Qg[r * 32 + c];
        }
    }

    auto loadKV = [&](int kt, int s) {
        const uint32_t *Kg = K + (hb + kt * 64) * 32;
        const uint32_t kb = smb + KS_OFF + s * 9216;
#pragma unroll
        for (int i = 0; i < 2; i++) {
            int id = tid + i * 256;
            int r = id >> 3, c = id & 7;
            cpa16(kb + r * LKB + c * 16, Kg + r * 32 + c * 4);
        }
        const uint32_t *Vg = V + (hb + kt * 64) * 32;
        const uint32_t vb = smb + VS_OFF + s * 9216;
#pragma unroll
        for (int i = 0; i < 2; i++) {
            int id = tid + i * 256;
            int r = id >> 3, c = id & 7;
            cpa16(vb + r * LKB + c * 16, Vg + r * 32 + c * 4);
        }
    };

    float accO[8][4];
#pragma unroll
    for (int i = 0; i < 8; i++)
#pragma unroll
        for (int j = 0; j < 4; j++) accO[i][j] = 0.f;
    float m0r = -1e30f, m1r = -1e30f, l0 = 0.f, l1 = 0.f;
    const int qlast = qt * 128 + w * 16 + 15;
    const int nkt = 2 * qt + 2;

    loadKV(0, 0);
    asm volatile("cp.async.commit_group;\n");

    for (int kt = 0; kt < nkt; ++kt) {
        const int s = kt & 1;
        __syncthreads();
        if (kt + 1 < nkt) {
            loadKV(kt + 1, s ^ 1);
            asm volatile("cp.async.commit_group;\n");
            asm volatile("cp.async.wait_group 1;\n");
        } else {
            asm volatile("cp.async.wait_group 0;\n");
        }
        __syncthreads();
        if (kt * 64 > qlast) continue;

        const uint32_t kaddr = smb + KS_OFF + s * 9216 + koff;
        const uint32_t vb = smb + VS_OFF + s * 9216;

        float sr[8][4];
#pragma unroll
        for (int nt = 0; nt < 8; nt++)
#pragma unroll
            for (int j = 0; j < 4; j++) sr[nt][j] = 0.f;

#pragma unroll
        for (int ks = 0; ks < 4; ks++) {
            const int so = ks * 8;
            const uint2 *ap = Qs + (w * 16 + gr) * LQ + so + gc;
            uint2 a0 = ap[0], a1 = ap[8 * LQ], a2 = ap[4], a3 = ap[8 * LQ + 4];
            const uint32_t ka = kaddr + ks * 32;
#pragma unroll
            for (int ntp = 0; ntp < 4; ntp++) {
                uint32_t kb0, kb1, kb2, kb3;
                ldmx4(kb0, kb1, kb2, kb3, ka + ntp * (16 * LKB));
                mma_f16(sr[2 * ntp], a0.x, a1.x, a2.x, a3.x, kb0, kb1);
                mma_f16(sr[2 * ntp], a0.y, a1.y, a2.y, a3.y, kb0, kb1);
                mma_f16(sr[2 * ntp + 1], a0.x, a1.x, a2.x, a3.x, kb2, kb3);
                mma_f16(sr[2 * ntp + 1], a0.y, a1.y, a2.y, a3.y, kb2, kb3);
            }
        }

        const bool needm = (kt * 64 + 63) > (qt * 128 + w * 16);
        if (needm) {
            const int qg0 = qt * 128 + w * 16 + gr;
#pragma unroll
            for (int nt = 0; nt < 8; nt++) {
                int kg = kt * 64 + nt * 8 + gc * 2;
#pragma unroll
                for (int j = 0; j < 4; j++)
                    if ((kg + (j & 1)) > (qg0 + ((j >> 1) << 3))) sr[nt][j] = -1e30f;
            }
        }
        float mx0 = -1e30f, mx1 = -1e30f;
#pragma unroll
        for (int nt = 0; nt < 8; nt++) {
            mx0 = fmaxf(mx0, fmaxf(sr[nt][0], sr[nt][1]));
            mx1 = fmaxf(mx1, fmaxf(sr[nt][2], sr[nt][3]));
        }
        mx0 = fmaxf(mx0, __shfl_xor_sync(0xffffffffu, mx0, 1));
        mx0 = fmaxf(mx0, __shfl_xor_sync(0xffffffffu, mx0, 2));
        mx1 = fmaxf(mx1, __shfl_xor_sync(0xffffffffu, mx1, 1));
        mx1 = fmaxf(mx1, __shfl_xor_sync(0xffffffffu, mx1, 2));
        float mn0 = fmaxf(m0r, mx0), mn1 = fmaxf(m1r, mx1);
        float alpha0 = __expf(m0r - mn0), alpha1 = __expf(m1r - mn1);
        m0r = mn0; m1r = mn1;

        float rs0 = 0.f, rs1 = 0.f;
#pragma unroll
        for (int nt = 0; nt < 8; nt++) {
            float p0 = __expf(sr[nt][0] - mn0);
            float p1 = __expf(sr[nt][1] - mn0);
            float p2 = __expf(sr[nt][2] - mn1);
            float p3 = __expf(sr[nt][3] - mn1);
            sr[nt][0] = p0; sr[nt][1] = p1; sr[nt][2] = p2; sr[nt][3] = p3;
            rs0 += p0 + p1;
            rs1 += p2 + p3;
        }
        rs0 += __shfl_xor_sync(0xffffffffu, rs0, 1);
        rs0 += __shfl_xor_sync(0xffffffffu, rs0, 2);
        rs1 += __shfl_xor_sync(0xffffffffu, rs1, 1);
        rs1 += __shfl_xor_sync(0xffffffffu, rs1, 2);
        l0 = l0 * alpha0 + rs0;
        l1 = l1 * alpha1 + rs1;
#pragma unroll
        for (int nt = 0; nt < 8; nt++) {
            accO[nt][0] *= alpha0; accO[nt][1] *= alpha0;
            accO[nt][2] *= alpha1; accO[nt][3] *= alpha1;
        }

#pragma unroll
        for (int t = 0; t < 4; t++) {
            uint32_t u0 = pack2h(sr[2 * t][0], sr[2 * t][1]);
            uint32_t u1 = pack2h(sr[2 * t][2], sr[2 * t][3]);
            uint32_t u2 = pack2h(sr[2 * t + 1][0], sr[2 * t + 1][1]);
            uint32_t u3 = pack2h(sr[2 * t + 1][2], sr[2 * t + 1][3]);
            const uint32_t rowoff = (t * 16 + vrow) * LKB + vcol * 2;
#pragma unroll
            for (int ntp = 0; ntp < 4; ntp++) {
                uint32_t bh0, bh1, bh2, bh3;
                ldmx4t(bh0, bh1, bh2, bh3, vb + rowoff + ntp * 32);
                mma_f16(accO[2 * ntp], u0, u1, u2, u3, bh0, bh1);
                mma_f16(accO[2 * ntp + 1], u0, u1, u2, u3, bh2, bh3);
            }
        }
    }

    float inv0 = 1.f / l0, inv1 = 1.f / l1;
    int b = bh >> 4, h = bh & 15;
    int q0 = qt * 128 + w * 16 + gr;
#pragma unroll
    for (int nt = 0; nt < 8; nt++) {
        int slot = h * 32 + nt * 4 + gc;
        O[((size_t)(b * SEQ + q0)) * 512 + slot] = pack2h(accO[nt][0] * inv0, accO[nt][1] * inv0);
        O[((size_t)(b * SEQ + q0 + 8)) * 512 + slot] = pack2h(accO[nt][2] * inv1, accO[nt][3] * inv1);
    }
}

// ---------- launch ----------
extern "C" void kernel_launch(void *const *d_in, const int *in_sizes, int n_in, void *d_out, int out_size) {
    const float *x = (const float *)d_in[0];
    const float *Wq = (const float *)d_in[1];
    const float *Wk = (const float *)d_in[2];
    const float *Wv = (const float *)d_in[3];
    const float *Wo = (const float *)d_in[4];
    float *out = (float *)d_out;

    uint2 *pQ;
    uint32_t *px1, *pW, *pK, *pV, *pA1;
    cudaGetSymbolAddress((void **)&px1, g_x1);
    cudaGetSymbolAddress((void **)&pW, g_Ws);
    cudaGetSymbolAddress((void **)&pQ, g_Q);
    cudaGetSymbolAddress((void **)&pK, g_K);
    cudaGetSymbolAddress((void **)&pV, g_V);
    cudaGetSymbolAddress((void **)&pA1, g_A1);

    cudaFuncSetAttribute(gemm_qkv_kernel, cudaFuncAttributeMaxDynamicSharedMemorySize, GEMM_SMEM);
    cudaFuncSetAttribute(gemm1_kernel, cudaFuncAttributeMaxDynamicSharedMemorySize, GEMM_SMEM);
    cudaFuncSetAttribute(attn_kernel, cudaFuncAttributeMaxDynamicSharedMemorySize, ATTN_SMEM);

    // launch 1: pack x; launch 2: pack all W
    pack_kernel<<<M_TOT * 512 / 256, 256>>>(x, px1, M_TOT * 512);
    split_w_kernel<<<4096, 256>>>(Wq, Wk, Wv, Wo, pW);
    // launch 3: fused QKV projection (1 mma/frag)
    gemm_qkv_kernel<<<dim3(24, 64), 256, GEMM_SMEM>>>(px1, pW, pQ, pK, pV);
    // launch 4: attention (profiled slot)
    attn_kernel<<<dim3(SEQ / 128, BATCH * N_HEADS), 256, ATTN_SMEM>>>(pQ, pK, pV, pA1);
    // launch 5: O projection (1 mma/frag)
    gemm1_kernel<<<dim3(8, 64), 256, GEMM_SMEM>>>(pA1, pW + (size_t)3 * 1024 * 512, out);
}

// round 16
// speedup vs baseline: 4.7335x; 1.1199x over previous
#include <cuda_runtime.h>
#include <cuda_fp16.h>
#include <cstdint>

#define D_MODEL 1024
#define N_HEADS 16
#define HEAD_DIM 64
#define BATCH 4
#define SEQ 2048
#define M_TOT 8192  // BATCH*SEQ

// ---- scratch (device globals per allocation-free rule) ----
__device__ uint32_t g_x1[M_TOT * 512];        // x single fp16 plane
__device__ uint32_t g_Ws[4 * 1024 * 512];     // W single fp16 plane (rows 0..4095)
__device__ uint32_t g_Q[M_TOT * 512];         // Q scatter (B,H,S,32 u32) single fp16, pre-scaled 0.125
__device__ uint32_t g_K[M_TOT * 512];         // K scatter single fp16
__device__ uint32_t g_V[M_TOT * 512];         // V scatter single fp16
__device__ uint32_t g_A1[M_TOT * 512];        // attention out single fp16 plane (B,S,512)

// ---------- helpers ----------
__device__ __forceinline__ uint32_t pack2h(float f0, float f1) {
    __half2 h = __floats2half2_rn(f0, f1);
    return *(uint32_t *)&h;
}

__device__ __forceinline__ void mma_f16(float c[4], uint32_t a0, uint32_t a1, uint32_t a2, uint32_t a3,
                                        uint32_t b0, uint32_t b1) {
    asm volatile(
        "mma.sync.aligned.m16n8k16.row.col.f32.f16.f16.f32 "
        "{%0,%1,%2,%3}, {%4,%5,%6,%7}, {%8,%9}, {%0,%1,%2,%3};\n"
        : "+f"(c[0]), "+f"(c[1]), "+f"(c[2]), "+f"(c[3])
        : "r"(a0), "r"(a1), "r"(a2), "r"(a3), "r"(b0), "r"(b1));
}

__device__ __forceinline__ void ldmx4(uint32_t &b0, uint32_t &b1, uint32_t &b2, uint32_t &b3, uint32_t addr) {
    asm volatile("ldmatrix.sync.aligned.m8n8.x4.shared.b16 {%0,%1,%2,%3}, [%4];"
                 : "=r"(b0), "=r"(b1), "=r"(b2), "=r"(b3)
                 : "r"(addr));
}

__device__ __forceinline__ void ldmx4t(uint32_t &b0, uint32_t &b1, uint32_t &b2, uint32_t &b3, uint32_t addr) {
    asm volatile("ldmatrix.sync.aligned.m8n8.x4.trans.shared.b16 {%0,%1,%2,%3}, [%4];"
                 : "=r"(b0), "=r"(b1), "=r"(b2), "=r"(b3)
                 : "r"(addr));
}

__device__ __forceinline__ void cpa16(uint32_t saddr, const void *g) {
    asm volatile("cp.async.cg.shared.global [%0], [%1], 16;\n" ::"r"(saddr), "l"(g));
}

// ---------- pack pass (x): fp32 -> single fp16 plane ----------
__global__ void __launch_bounds__(256) pack_kernel(const float *__restrict__ src, uint32_t *__restrict__ dst,
                                                   int npairs) {
    int i = blockIdx.x * 256 + threadIdx.x;
    if (i < npairs) {
        float2 f = *(const float2 *)(src + 2 * (size_t)i);
        dst[i] = pack2h(f.x, f.y);
    }
}

// ---------- pack pass (all 4 W, single fp16 plane) ----------
__global__ void __launch_bounds__(256) split_w_kernel(const float *__restrict__ W0, const float *__restrict__ W1,
                                                      const float *__restrict__ W2, const float *__restrict__ W3,
                                                      uint32_t *__restrict__ dst) {
    int row = blockIdx.x;  // 0..4095
    const float *W = (row < 1024) ? W0 : (row < 2048) ? W1 : (row < 3072) ? W2 : W3;
    const float2 *src = (const float2 *)(W + (size_t)(row & 1023) * 1024);
    uint32_t *d = dst + (size_t)row * 512;
#pragma unroll
    for (int j = threadIdx.x; j < 512; j += 256) {
        float2 f = src[j];
        d[j] = pack2h(f.x, f.y);
    }
}

#define LDB 20        // smem row stride in u32 (16 data + 4 pad)
#define G_STG 10240   // one plane stage: 128 rows x 20 u32 x 4B
#define GEMM_SMEM (4 * G_STG)

// ---------- GEMM (QKV): single fp16 x single fp16, 1 mma/frag; fused QKV routing ----------
__global__ void __launch_bounds__(256) gemm_qkv_kernel(const uint32_t *__restrict__ A, const uint32_t *__restrict__ B,
                                                       void *__restrict__ C0, void *__restrict__ C1,
                                                       void *__restrict__ C2) {
    extern __shared__ uint32_t smg[];
    uint32_t smb;
    asm("{ .reg .u64 t; cvta.to.shared.u64 t, %1; cvt.u32.u64 %0, t; }" : "=r"(smb) : "l"(smg));
    const int tid = threadIdx.x, lane = tid & 31, w = tid >> 5;
    const int m0 = blockIdx.y * 128, n0 = blockIdx.x * 128;
    const int wm = (w >> 2) * 64, wn = (w & 3) * 32;
    const int gr = lane >> 2, gc = lane & 3;

    float acc[4][4][4];
#pragma unroll
    for (int i = 0; i < 4; i++)
#pragma unroll
        for (int j = 0; j < 4; j++)
#pragma unroll
            for (int k = 0; k < 4; k++) acc[i][j][k] = 0.f;

    auto load = [&](int kt, int stg) {
        const uint32_t *Ag = A + (size_t)m0 * 512 + kt * 16;
        const uint32_t *Bg = B + (size_t)n0 * 512 + kt * 16;
        uint32_t Ad = smb + stg * 2 * G_STG;
        uint32_t Bd = Ad + G_STG;
#pragma unroll
        for (int i = 0; i < 2; i++) {
            int id = tid + i * 256;
            int r = id >> 2, c = (id & 3) * 4;
            cpa16(Ad + (r * LDB + c) * 4, Ag + (size_t)r * 512 + c);
            cpa16(Bd + (r * LDB + c) * 4, Bg + (size_t)r * 512 + c);
        }
    };

    load(0, 0);
    asm volatile("cp.async.commit_group;\n");

    for (int kt = 0; kt < 32; ++kt) {
        asm volatile("cp.async.wait_group 0;\n");
        __syncthreads();
        if (kt + 1 < 32) {
            load(kt + 1, (kt + 1) & 1);
            asm volatile("cp.async.commit_group;\n");
        }
        const uint32_t *Ad = smg + (kt & 1) * 2 * (G_STG / 4);
        const uint32_t *Bd = Ad + G_STG / 4;
#pragma unroll
        for (int ks = 0; ks < 2; ks++) {
            const int so = ks * 8;
            uint32_t au[4][4], bu[4][2];
#pragma unroll
            for (int im = 0; im < 4; im++) {
                const uint32_t *p = Ad + (wm + im * 16 + gr) * LDB + so + gc;
                au[im][0] = p[0]; au[im][1] = p[8 * LDB];
                au[im][2] = p[4]; au[im][3] = p[8 * LDB + 4];
            }
#pragma unroll
            for (int in = 0; in < 4; in++) {
                const uint32_t *p = Bd + (wn + in * 8 + gr) * LDB + so + gc;
                bu[in][0] = p[0];
                bu[in][1] = p[4];
            }
#pragma unroll
            for (int im = 0; im < 4; im++)
#pragma unroll
                for (int in = 0; in < 4; in++)
                    mma_f16(acc[im][in], au[im][0], au[im][1], au[im][2], au[im][3], bu[in][0], bu[in][1]);
        }
        __syncthreads();
    }

#pragma unroll
    for (int im = 0; im < 4; im++)
#pragma unroll
        for (int in = 0; in < 4; in++) {
            int gm = m0 + wm + im * 16 + gr;
            int gn = n0 + wn + in * 8 + gc * 2;
            float c0 = acc[im][in][0], c1 = acc[im][in][1], c2 = acc[im][in][2], c3 = acc[im][in][3];
            int mat = gn >> 10;  // 0=Q, 1=K, 2=V
            int gnl = gn & 1023;
            int b = gm >> 11, s2 = gm & 2047, h = gnl >> 6, dd = gnl & 63;
            size_t idx = ((size_t)((b << 4) | h) * 2048 + s2) * 32 + (dd >> 1);
            if (mat == 0) {
                // Q: fold softmax scale 1/sqrt(64) = 0.125 (exact), single fp16
                uint32_t *Qp = (uint32_t *)C0;
                Qp[idx] = pack2h(c0 * 0.125f, c1 * 0.125f);
                Qp[idx + 8 * 32] = pack2h(c2 * 0.125f, c3 * 0.125f);
            } else if (mat == 1) {
                uint32_t *Kp = (uint32_t *)C1;
                Kp[idx] = pack2h(c0, c1);
                Kp[idx + 8 * 32] = pack2h(c2, c3);
            } else {
                uint32_t *Vp = (uint32_t *)C2;
                Vp[idx] = pack2h(c0, c1);
                Vp[idx + 8 * 32] = pack2h(c2, c3);
            }
        }
}

// ---------- GEMM1 (O-proj): single x single, 1 mma/frag, fp32 out ----------
__global__ void __launch_bounds__(256) gemm1_kernel(const uint32_t *__restrict__ A, const uint32_t *__restrict__ B,
                                                    float *__restrict__ C) {
    extern __shared__ uint32_t smg1[];
    uint32_t smb;
    asm("{ .reg .u64 t; cvta.to.shared.u64 t, %1; cvt.u32.u64 %0, t; }" : "=r"(smb) : "l"(smg1));
    const int tid = threadIdx.x, lane = tid & 31, w = tid >> 5;
    const int m0 = blockIdx.y * 128, n0 = blockIdx.x * 128;
    const int wm = (w >> 2) * 64, wn = (w & 3) * 32;
    const int gr = lane >> 2, gc = lane & 3;

    float acc[4][4][4];
#pragma unroll
    for (int i = 0; i < 4; i++)
#pragma unroll
        for (int j = 0; j < 4; j++)
#pragma unroll
            for (int k = 0; k < 4; k++) acc[i][j][k] = 0.f;

    auto load = [&](int kt, int stg) {
        const uint32_t *Ag = A + (size_t)m0 * 512 + kt * 16;
        const uint32_t *Bg = B + (size_t)n0 * 512 + kt * 16;
        uint32_t Ad = smb + stg * 2 * G_STG;
        uint32_t Bd = Ad + G_STG;
#pragma unroll
        for (int i = 0; i < 2; i++) {
            int id = tid + i * 256;
            int r = id >> 2, c = (id & 3) * 4;
            cpa16(Ad + (r * LDB + c) * 4, Ag + (size_t)r * 512 + c);
            cpa16(Bd + (r * LDB + c) * 4, Bg + (size_t)r * 512 + c);
        }
    };

    load(0, 0);
    asm volatile("cp.async.commit_group;\n");

    for (int kt = 0; kt < 32; ++kt) {
        asm volatile("cp.async.wait_group 0;\n");
        __syncthreads();
        if (kt + 1 < 32) {
            load(kt + 1, (kt + 1) & 1);
            asm volatile("cp.async.commit_group;\n");
        }
        const uint32_t *Ad = smg1 + (kt & 1) * 2 * (G_STG / 4);
        const uint32_t *Bd = Ad + G_STG / 4;
#pragma unroll
        for (int ks = 0; ks < 2; ks++) {
            const int so = ks * 8;
            uint32_t au[4][4], bu[4][2];
#pragma unroll
            for (int im = 0; im < 4; im++) {
                const uint32_t *p = Ad + (wm + im * 16 + gr) * LDB + so + gc;
                au[im][0] = p[0]; au[im][1] = p[8 * LDB];
                au[im][2] = p[4]; au[im][3] = p[8 * LDB + 4];
            }
#pragma unroll
            for (int in = 0; in < 4; in++) {
                const uint32_t *p = Bd + (wn + in * 8 + gr) * LDB + so + gc;
                bu[in][0] = p[0];
                bu[in][1] = p[4];
            }
#pragma unroll
            for (int im = 0; im < 4; im++)
#pragma unroll
                for (int in = 0; in < 4; in++)
                    mma_f16(acc[im][in], au[im][0], au[im][1], au[im][2], au[im][3], bu[in][0], bu[in][1]);
        }
        __syncthreads();
    }

#pragma unroll
    for (int im = 0; im < 4; im++)
#pragma unroll
        for (int in = 0; in < 4; in++) {
            int gm = m0 + wm + im * 16 + gr;
            int gn = n0 + wn + in * 8 + gc * 2;
            *(float2 *)(C + (size_t)gm * 1024 + gn) = make_float2(acc[im][in][0], acc[im][in][1]);
            *(float2 *)(C + (size_t)(gm + 8) * 1024 + gn) = make_float2(acc[im][in][2], acc[im][in][3]);
        }
}

// ---------- Flash attention: all-single fp16, 1-mma QK + 1-mma PV, ldmatrix everywhere ----------
#define LKB 144  // Q/K/V smem row stride in bytes (64 fp16 + 8 pad)
#define KS_OFF 18432
#define VS_OFF 36864
#define ATTN_SMEM 55296

__global__ void __launch_bounds__(256, 2) attn_kernel(const uint32_t *__restrict__ Q, const uint32_t *__restrict__ K,
                                                      const uint32_t *__restrict__ V, uint32_t *__restrict__ O) {
    extern __shared__ char smab[];
    uint32_t smb;
    asm("{ .reg .u64 t; cvta.to.shared.u64 t, %1; cvt.u32.u64 %0, t; }" : "=r"(smb) : "l"(smab));
    const int tid = threadIdx.x, lane = tid & 31, w = tid >> 5;
    const int qt = (int)gridDim.x - 1 - (int)blockIdx.x;  // long CTAs first
    const int bh = blockIdx.y;
    const int gr = lane >> 2, gc = lane & 3;
    const size_t hb = (size_t)bh * SEQ;
    // V ldmatrix.trans lane addressing
    const uint32_t vrow = ((lane >> 3) & 1) * 8 + (lane & 7);
    const uint32_t vcol = (lane >> 4) * 8;
    // K ldmatrix (non-trans) B-frag addressing
    const uint32_t krow = ((lane >> 4) << 3) + (lane & 7);
    const uint32_t koff = krow * LKB + (((lane >> 3) & 1) << 4);
    // Q ldmatrix (non-trans) A-frag addressing: tiles [q0-7 kLo, q8-15 kLo, q0-7 kHi, q8-15 kHi]
    const uint32_t qoff = (w * 16 + (lane & 15)) * LKB + ((lane >> 4) << 4);

    {  // Q tile once (cp.async, joined with first KV group)
        const uint32_t *Qg = Q + (hb + qt * 128) * 32;
#pragma unroll
        for (int i = 0; i < 4; i++) {  // 128 rows x 8 chunks of 16B
            int id = tid + i * 256;
            int r = id >> 3, c = id & 7;
            cpa16(smb + r * LKB + c * 16, Qg + r * 32 + c * 4);
        }
    }

    auto loadKV = [&](int kt, int s) {
        const uint32_t *Kg = K + (hb + kt * 64) * 32;
        const uint32_t kb = smb + KS_OFF + s * 9216;
#pragma unroll
        for (int i = 0; i < 2; i++) {
            int id = tid + i * 256;
            int r = id >> 3, c = id & 7;
            cpa16(kb + r * LKB + c * 16, Kg + r * 32 + c * 4);
        }
        const uint32_t *Vg = V + (hb + kt * 64) * 32;
        const uint32_t vb = smb + VS_OFF + s * 9216;
#pragma unroll
        for (int i = 0; i < 2; i++) {
            int id = tid + i * 256;
            int r = id >> 3, c = id & 7;
            cpa16(vb + r * LKB + c * 16, Vg + r * 32 + c * 4);
        }
    };

    float accO[8][4];
#pragma unroll
    for (int i = 0; i < 8; i++)
#pragma unroll
        for (int j = 0; j < 4; j++) accO[i][j] = 0.f;
    float m0r = -1e30f, m1r = -1e30f, l0 = 0.f, l1 = 0.f;
    const int qlast = qt * 128 + w * 16 + 15;
    const int nkt = 2 * qt + 2;

    loadKV(0, 0);
    asm volatile("cp.async.commit_group;\n");

    for (int kt = 0; kt < nkt; ++kt) {
        const int s = kt & 1;
        __syncthreads();
        if (kt + 1 < nkt) {
            loadKV(kt + 1, s ^ 1);
            asm volatile("cp.async.commit_group;\n");
            asm volatile("cp.async.wait_group 1;\n");
        } else {
            asm volatile("cp.async.wait_group 0;\n");
        }
        __syncthreads();
        if (kt * 64 > qlast) continue;

        const uint32_t kaddr = smb + KS_OFF + s * 9216 + koff;
        const uint32_t vb = smb + VS_OFF + s * 9216;

        // S = Q K^T : 1 ldmatrix.x4 (Q A-frag) + 4 ldmatrix.x4 (K) + 8 mma per ks
        float sr[8][4];
#pragma unroll
        for (int nt = 0; nt < 8; nt++)
#pragma unroll
            for (int j = 0; j < 4; j++) sr[nt][j] = 0.f;

#pragma unroll
        for (int ks = 0; ks < 4; ks++) {
            uint32_t a0, a1, a2, a3;
            ldmx4(a0, a1, a2, a3, smb + qoff + ks * 32);
            const uint32_t ka = kaddr + ks * 32;
#pragma unroll
            for (int ntp = 0; ntp < 4; ntp++) {
                uint32_t kb0, kb1, kb2, kb3;
                ldmx4(kb0, kb1, kb2, kb3, ka + ntp * (16 * LKB));
                mma_f16(sr[2 * ntp], a0, a1, a2, a3, kb0, kb1);
                mma_f16(sr[2 * ntp + 1], a0, a1, a2, a3, kb2, kb3);
            }
        }

        // causal mask (diagonal tiles only) + row stats
        const bool needm = (kt * 64 + 63) > (qt * 128 + w * 16);
        if (needm) {
            const int qg0 = qt * 128 + w * 16 + gr;
#pragma unroll
            for (int nt = 0; nt < 8; nt++) {
                int kg = kt * 64 + nt * 8 + gc * 2;
#pragma unroll
                for (int j = 0; j < 4; j++)
                    if ((kg + (j & 1)) > (qg0 + ((j >> 1) << 3))) sr[nt][j] = -1e30f;
            }
        }
        float mx0 = -1e30f, mx1 = -1e30f;
#pragma unroll
        for (int nt = 0; nt < 8; nt++) {
            mx0 = fmaxf(mx0, fmaxf(sr[nt][0], sr[nt][1]));
            mx1 = fmaxf(mx1, fmaxf(sr[nt][2], sr[nt][3]));
        }
        mx0 = fmaxf(mx0, __shfl_xor_sync(0xffffffffu, mx0, 1));
        mx0 = fmaxf(mx0, __shfl_xor_sync(0xffffffffu, mx0, 2));
        mx1 = fmaxf(mx1, __shfl_xor_sync(0xffffffffu, mx1, 1));
        mx1 = fmaxf(mx1, __shfl_xor_sync(0xffffffffu, mx1, 2));
        float mn0 = fmaxf(m0r, mx0), mn1 = fmaxf(m1r, mx1);
        float alpha0 = __expf(m0r - mn0), alpha1 = __expf(m1r - mn1);
        m0r = mn0; m1r = mn1;

        float rs0 = 0.f, rs1 = 0.f;
#pragma unroll
        for (int nt = 0; nt < 8; nt++) {
            float p0 = __expf(sr[nt][0] - mn0);
            float p1 = __expf(sr[nt][1] - mn0);
            float p2 = __expf(sr[nt][2] - mn1);
            float p3 = __expf(sr[nt][3] - mn1);
            sr[nt][0] = p0; sr[nt][1] = p1; sr[nt][2] = p2; sr[nt][3] = p3;
            rs0 += p0 + p1;
            rs1 += p2 + p3;
        }
        rs0 += __shfl_xor_sync(0xffffffffu, rs0, 1);
        rs0 += __shfl_xor_sync(0xffffffffu, rs0, 2);
        rs1 += __shfl_xor_sync(0xffffffffu, rs1, 1);
        rs1 += __shfl_xor_sync(0xffffffffu, rs1, 2);
        l0 = l0 * alpha0 + rs0;
        l1 = l1 * alpha1 + rs1;
#pragma unroll
        for (int nt = 0; nt < 8; nt++) {
            accO[nt][0] *= alpha0; accO[nt][1] *= alpha0;
            accO[nt][2] *= alpha1; accO[nt][3] *= alpha1;
        }

        // O += P V  (P single fp16; V via ldmatrix.x4.trans)
#pragma unroll
        for (int t = 0; t < 4; t++) {
            uint32_t u0 = pack2h(sr[2 * t][0], sr[2 * t][1]);
            uint32_t u1 = pack2h(sr[2 * t][2], sr[2 * t][3]);
            uint32_t u2 = pack2h(sr[2 * t + 1][0], sr[2 * t + 1][1]);
            uint32_t u3 = pack2h(sr[2 * t + 1][2], sr[2 * t + 1][3]);
            const uint32_t rowoff = (t * 16 + vrow) * LKB + vcol * 2;
#pragma unroll
            for (int ntp = 0; ntp < 4; ntp++) {
                uint32_t bh0, bh1, bh2, bh3;
                ldmx4t(bh0, bh1, bh2, bh3, vb + rowoff + ntp * 32);
                mma_f16(accO[2 * ntp], u0, u1, u2, u3, bh0, bh1);
                mma_f16(accO[2 * ntp + 1], u0, u1, u2, u3, bh2, bh3);
            }
        }
    }

    // epilogue: write single fp16 plane, concat layout (B,S,512)
    float inv0 = 1.f / l0, inv1 = 1.f / l1;
    int b = bh >> 4, h = bh & 15;
    int q0 = qt * 128 + w * 16 + gr;
#pragma unroll
    for (int nt = 0; nt < 8; nt++) {
        int slot = h * 32 + nt * 4 + gc;
        O[((size_t)(b * SEQ + q0)) * 512 + slot] = pack2h(accO[nt][0] * inv0, accO[nt][1] * inv0);
        O[((size_t)(b * SEQ + q0 + 8)) * 512 + slot] = pack2h(accO[nt][2] * inv1, accO[nt][3] * inv1);
    }
}

// ---------- launch ----------
extern "C" void kernel_launch(void *const *d_in, const int *in_sizes, int n_in, void *d_out, int out_size) {
    const float *x = (const float *)d_in[0];
    const float *Wq = (const float *)d_in[1];
    const float *Wk = (const float *)d_in[2];
    const float *Wv = (const float *)d_in[3];
    const float *Wo = (const float *)d_in[4];
    float *out = (float *)d_out;

    uint32_t *px1, *pW, *pQ, *pK, *pV, *pA1;
    cudaGetSymbolAddress((void **)&px1, g_x1);
    cudaGetSymbolAddress((void **)&pW, g_Ws);
    cudaGetSymbolAddress((void **)&pQ, g_Q);
    cudaGetSymbolAddress((void **)&pK, g_K);
    cudaGetSymbolAddress((void **)&pV, g_V);
    cudaGetSymbolAddress((void **)&pA1, g_A1);

    cudaFuncSetAttribute(gemm_qkv_kernel, cudaFuncAttributeMaxDynamicSharedMemorySize, GEMM_SMEM);
    cudaFuncSetAttribute(gemm1_kernel, cudaFuncAttributeMaxDynamicSharedMemorySize, GEMM_SMEM);
    cudaFuncSetAttribute(attn_kernel, cudaFuncAttributeMaxDynamicSharedMemorySize, ATTN_SMEM);

    // launch 1: pack x; launch 2: pack all W
    pack_kernel<<<M_TOT * 512 / 256, 256>>>(x, px1, M_TOT * 512);
    split_w_kernel<<<4096, 256>>>(Wq, Wk, Wv, Wo, pW);
    // launch 3: fused QKV projection (1 mma/frag)
    gemm_qkv_kernel<<<dim3(24, 64), 256, GEMM_SMEM>>>(px1, pW, pQ, pK, pV);
    // launch 4: attention (profiled slot)
    attn_kernel<<<dim3(SEQ / 128, BATCH * N_HEADS), 256, ATTN_SMEM>>>(pQ, pK, pV, pA1);
    // launch 5: O projection (1 mma/frag)
    gemm1_kernel<<<dim3(8, 64), 256, GEMM_SMEM>>>(pA1, pW + (size_t)3 * 1024 * 512, out);
}